// round 1
// baseline (speedup 1.0000x reference)
#include <cuda_runtime.h>

// Problem constants
#define GB 8
#define GN 16384
#define GC 256
#define GH 8
#define GD 64
#define GHD 512
#define GM (GB*GN)          // 131072 flattened rows

// ---------------- scratch (device globals; no allocation allowed) ----------
__device__ float g_q[(size_t)GM * GHD];   // raw Q projection
__device__ float g_k[(size_t)GM * GHD];   // raw K projection
__device__ float g_v[(size_t)GM * GHD];   // raw V projection

#define CHUNKS 16
#define LCHUNK (GN / CHUNKS)              // 1024
// per (chunk, b*h): 4096 kv + 64 ksum + 64 vsum = 4224 floats
__device__ float g_kvpart[(size_t)CHUNKS * 64 * 4224];
__device__ float g_kvred[(size_t)64 * 4224];

// ---------------- SGEMM: out[M,512] = A[M,256] @ W[256,512] + bias ---------
#define BM 128
#define BN 128
#define BK 16
#define TM 8
#define TN 8

__global__ __launch_bounds__(256) void sgemm_bias_kernel(
    const float* __restrict__ A, const float* __restrict__ W,
    const float* __restrict__ bias, float* __restrict__ out)
{
    const int K = GC;    // 256
    const int N = GHD;   // 512

    __shared__ float As[BK][BM];   // transposed A tile
    __shared__ float Bs[BK][BN];

    int tid  = threadIdx.x;
    int trow = tid >> 4;   // 0..15
    int tcol = tid & 15;   // 0..15

    const float* Ab = A + (size_t)blockIdx.x * BM * K;
    const float* Wb = W + blockIdx.y * BN;

    float acc[TM][TN];
#pragma unroll
    for (int i = 0; i < TM; i++)
#pragma unroll
        for (int j = 0; j < TN; j++) acc[i][j] = 0.f;

    for (int k0 = 0; k0 < K; k0 += BK) {
        // A tile: 128 rows x 16 k  (512 float4, 2 per thread), store transposed
#pragma unroll
        for (int t = 0; t < 2; t++) {
            int idx = tid + t * 256;          // 0..511
            int r   = idx >> 2;               // 0..127
            int c4  = (idx & 3) << 2;         // 0,4,8,12
            float4 a = *(const float4*)(Ab + (size_t)r * K + k0 + c4);
            As[c4 + 0][r] = a.x;
            As[c4 + 1][r] = a.y;
            As[c4 + 2][r] = a.z;
            As[c4 + 3][r] = a.w;
        }
        // B tile: 16 rows x 128 cols (512 float4, 2 per thread)
#pragma unroll
        for (int t = 0; t < 2; t++) {
            int idx = tid + t * 256;
            int r   = idx >> 5;               // 0..15
            int c4  = (idx & 31) << 2;        // 0..124
            *(float4*)&Bs[r][c4] = *(const float4*)(Wb + (size_t)(k0 + r) * N + c4);
        }
        __syncthreads();

#pragma unroll
        for (int kk = 0; kk < BK; kk++) {
            float ra[TM], rb[TN];
            float4 a0 = *(const float4*)&As[kk][trow * TM];
            float4 a1 = *(const float4*)&As[kk][trow * TM + 4];
            ra[0] = a0.x; ra[1] = a0.y; ra[2] = a0.z; ra[3] = a0.w;
            ra[4] = a1.x; ra[5] = a1.y; ra[6] = a1.z; ra[7] = a1.w;
            float4 b0 = *(const float4*)&Bs[kk][tcol * TN];
            float4 b1 = *(const float4*)&Bs[kk][tcol * TN + 4];
            rb[0] = b0.x; rb[1] = b0.y; rb[2] = b0.z; rb[3] = b0.w;
            rb[4] = b1.x; rb[5] = b1.y; rb[6] = b1.z; rb[7] = b1.w;
#pragma unroll
            for (int i = 0; i < TM; i++)
#pragma unroll
                for (int j = 0; j < TN; j++)
                    acc[i][j] += ra[i] * rb[j];
        }
        __syncthreads();
    }

    // epilogue with bias
#pragma unroll
    for (int i = 0; i < TM; i++) {
        size_t row = (size_t)blockIdx.x * BM + trow * TM + i;
#pragma unroll
        for (int j = 0; j < TN; j += 4) {
            int col = blockIdx.y * BN + tcol * TN + j;
            float4 o;
            o.x = acc[i][j + 0] + bias[col + 0];
            o.y = acc[i][j + 1] + bias[col + 1];
            o.z = acc[i][j + 2] + bias[col + 2];
            o.w = acc[i][j + 3] + bias[col + 3];
            *(float4*)(out + row * N + col) = o;
        }
    }
}

// ---------------- reduce stage 1: partial kv / ksum / vsum -----------------
// grid (CHUNKS, 64 b*h), block 256.  Normalizes k rows on the fly.
#define RROWS 8

__global__ __launch_bounds__(256) void reduce_stage1(void)
{
    int chunk = blockIdx.x;
    int bh    = blockIdx.y;
    int b = bh >> 3, h = bh & 7;

    __shared__ float sk[RROWS][64];
    __shared__ float sv[RROWS][64];

    int tid  = threadIdx.x;
    int m    = tid & 63;        // 0..63
    int dg   = tid >> 6;        // 0..3 -> d slice [dg*16, dg*16+16)
    int lane = tid & 31, warp = tid >> 5;

    const float* kbase = g_k + (size_t)b * GN * GHD + h * GD;
    const float* vbase = g_v + (size_t)b * GN * GHD + h * GD;

    float acc[16];
#pragma unroll
    for (int j = 0; j < 16; j++) acc[j] = 0.f;
    float sacc = 0.f;   // ksum (dg==0) or vsum (dg==1)

    int lend = (chunk + 1) * LCHUNK;
    for (int l0 = chunk * LCHUNK; l0 < lend; l0 += RROWS) {
#pragma unroll
        for (int t = 0; t < 2; t++) {
            int idx = tid + t * 256;      // 0..511
            int r = idx >> 6, c = idx & 63;
            sk[r][c] = kbase[(size_t)(l0 + r) * GHD + c];
            sv[r][c] = vbase[(size_t)(l0 + r) * GHD + c];
        }
        __syncthreads();
        // warp w normalizes row w (64 elems, 2 per lane)
        {
            float x0 = sk[warp][lane], x1 = sk[warp][lane + 32];
            float ss = x0 * x0 + x1 * x1;
#pragma unroll
            for (int o = 16; o > 0; o >>= 1)
                ss += __shfl_xor_sync(0xffffffffu, ss, o);
            float inv = rsqrtf(ss);
            sk[warp][lane]      = x0 * inv;
            sk[warp][lane + 32] = x1 * inv;
        }
        __syncthreads();
#pragma unroll
        for (int r = 0; r < RROWS; r++) {
            float kval = sk[r][m];
            float4 v0 = *(const float4*)&sv[r][dg * 16 + 0];
            float4 v1 = *(const float4*)&sv[r][dg * 16 + 4];
            float4 v2 = *(const float4*)&sv[r][dg * 16 + 8];
            float4 v3 = *(const float4*)&sv[r][dg * 16 + 12];
            acc[0]  += kval * v0.x; acc[1]  += kval * v0.y;
            acc[2]  += kval * v0.z; acc[3]  += kval * v0.w;
            acc[4]  += kval * v1.x; acc[5]  += kval * v1.y;
            acc[6]  += kval * v1.z; acc[7]  += kval * v1.w;
            acc[8]  += kval * v2.x; acc[9]  += kval * v2.y;
            acc[10] += kval * v2.z; acc[11] += kval * v2.w;
            acc[12] += kval * v3.x; acc[13] += kval * v3.y;
            acc[14] += kval * v3.z; acc[15] += kval * v3.w;
            if (dg == 0)      sacc += kval;
            else if (dg == 1) sacc += sv[r][m];
        }
        __syncthreads();
    }

    float* dst = g_kvpart + ((size_t)chunk * 64 + bh) * 4224;
#pragma unroll
    for (int j = 0; j < 16; j++) dst[m * 64 + dg * 16 + j] = acc[j];
    if (dg == 0)      dst[4096 + m] = sacc;
    else if (dg == 1) dst[4160 + m] = sacc;
}

// ---------------- reduce stage 2: deterministic partial sum ----------------
__global__ void reduce_stage2(void)
{
    int i = blockIdx.x * blockDim.x + threadIdx.x;   // 0 .. 64*4224-1
    if (i >= 64 * 4224) return;
    float s = 0.f;
#pragma unroll
    for (int c = 0; c < CHUNKS; c++)
        s += g_kvpart[(size_t)c * 64 * 4224 + i];
    g_kvred[i] = s;
}

// ---------------- final: normalize q, matvec with kv, rational, head mean --
#define FROWS 64

__global__ __launch_bounds__(256) void final_kernel(float* __restrict__ out)
{
    __shared__ float sq[FROWS][GD];     // normalized q slice for current head
    __shared__ float skv[GD][GD];       // kv for current head
    __shared__ float sksum[GD];
    __shared__ float svsum[GD];
    __shared__ float sden[FROWS];

    int tid  = threadIdx.x;
    int dq   = tid & 15;        // d block: dq*4 .. +4
    int rg   = tid >> 4;        // 0..15 -> rows rg*4 .. +4
    int lane = tid & 31, warp = tid >> 5;

    size_t row0 = (size_t)blockIdx.x * FROWS;
    int b = (int)(row0 / GN);   // FROWS divides GN, block stays in one batch
    const float* qbase = g_q + row0 * GHD;
    const float Nf = (float)GN;

    float outacc[4][4];
#pragma unroll
    for (int i = 0; i < 4; i++)
#pragma unroll
        for (int j = 0; j < 4; j++) outacc[i][j] = 0.f;

    for (int h = 0; h < GH; h++) {
        const float* kvb = g_kvred + (size_t)(b * GH + h) * 4224;
        // kv: 4096 floats = 1024 float4, 4 per thread
#pragma unroll
        for (int t = 0; t < 4; t++)
            ((float4*)skv)[tid + t * 256] = ((const float4*)kvb)[tid + t * 256];
        if (tid < 64)        sksum[tid]      = kvb[4096 + tid];
        else if (tid < 128)  svsum[tid - 64] = kvb[4096 + tid];  // 4160..4223
        // q slice: 64 rows x 64 cols
#pragma unroll
        for (int t = 0; t < 16; t++) {
            int idx = tid + t * 256;
            int r = idx >> 6, c = idx & 63;
            sq[r][c] = qbase[(size_t)r * GHD + h * GD + c];
        }
        __syncthreads();

        // normalize: warp w handles rows w*8 .. w*8+7
#pragma unroll
        for (int rr = 0; rr < 8; rr++) {
            int r = warp * 8 + rr;
            float x0 = sq[r][lane], x1 = sq[r][lane + 32];
            float ss = x0 * x0 + x1 * x1;
#pragma unroll
            for (int o = 16; o > 0; o >>= 1)
                ss += __shfl_xor_sync(0xffffffffu, ss, o);
            float inv = rsqrtf(ss);
            sq[r][lane]      = x0 * inv;
            sq[r][lane + 32] = x1 * inv;
        }
        __syncthreads();

        // denominator per row: q . ksum + 2N
#pragma unroll
        for (int rr = 0; rr < 8; rr++) {
            int r = warp * 8 + rr;
            float p = sq[r][lane] * sksum[lane] + sq[r][lane + 32] * sksum[lane + 32];
#pragma unroll
            for (int o = 16; o > 0; o >>= 1)
                p += __shfl_xor_sync(0xffffffffu, p, o);
            if (lane == 0) sden[r] = p + 2.f * Nf;
        }
        __syncthreads();

        // 4 rows x 4 d register-tiled matvec over m
        float a[4][4];
#pragma unroll
        for (int i = 0; i < 4; i++)
#pragma unroll
            for (int j = 0; j < 4; j++) a[i][j] = 0.f;

        for (int m = 0; m < GD; m++) {
            float4 kvv = *(const float4*)&skv[m][dq * 4];
#pragma unroll
            for (int i = 0; i < 4; i++) {
                float qv = sq[rg * 4 + i][m];
                a[i][0] += qv * kvv.x;
                a[i][1] += qv * kvv.y;
                a[i][2] += qv * kvv.z;
                a[i][3] += qv * kvv.w;
            }
        }
        float4 vsv = *(const float4*)&svsum[dq * 4];
#pragma unroll
        for (int i = 0; i < 4; i++) {
            float rden = 1.f / sden[rg * 4 + i];
            outacc[i][0] += (a[i][0] + Nf * vsv.x) * rden;
            outacc[i][1] += (a[i][1] + Nf * vsv.y) * rden;
            outacc[i][2] += (a[i][2] + Nf * vsv.z) * rden;
            outacc[i][3] += (a[i][3] + Nf * vsv.w) * rden;
        }
        __syncthreads();   // before next head overwrites smem
    }

    // mean over heads, write [B,N,64]
#pragma unroll
    for (int i = 0; i < 4; i++) {
        float4 o;
        o.x = outacc[i][0] * (1.f / GH);
        o.y = outacc[i][1] * (1.f / GH);
        o.z = outacc[i][2] * (1.f / GH);
        o.w = outacc[i][3] * (1.f / GH);
        *(float4*)(out + (row0 + rg * 4 + i) * GD + dq * 4) = o;
    }
}

// ---------------- launch ---------------------------------------------------
extern "C" void kernel_launch(void* const* d_in, const int* in_sizes, int n_in,
                              void* d_out, int out_size)
{
    const float* q_in = (const float*)d_in[0];
    const float* s_in = (const float*)d_in[1];
    const float* Wq   = (const float*)d_in[2];
    const float* bq   = (const float*)d_in[3];
    const float* Wk   = (const float*)d_in[4];
    const float* bk   = (const float*)d_in[5];
    const float* Wv   = (const float*)d_in[6];
    const float* bv   = (const float*)d_in[7];
    float* out = (float*)d_out;

    float *gq, *gk, *gv;
    cudaGetSymbolAddress((void**)&gq, g_q);
    cudaGetSymbolAddress((void**)&gk, g_k);
    cudaGetSymbolAddress((void**)&gv, g_v);

    dim3 ggrid(GM / BM, GHD / BN);   // (1024, 4)
    sgemm_bias_kernel<<<ggrid, 256>>>(q_in, Wq, bq, gq);
    sgemm_bias_kernel<<<ggrid, 256>>>(s_in, Wk, bk, gk);
    sgemm_bias_kernel<<<ggrid, 256>>>(s_in, Wv, bv, gv);

    reduce_stage1<<<dim3(CHUNKS, 64), 256>>>();
    reduce_stage2<<<(64 * 4224 + 255) / 256, 256>>>();

    final_kernel<<<GM / FROWS, 256>>>(out);
}

// round 4
// speedup vs baseline: 1.6230x; 1.6230x over previous
#include <cuda_runtime.h>
#include <cuda_bf16.h>
#include <cstdint>

// Problem constants
#define GB 8
#define GN 16384
#define GC 256
#define GH 8
#define GD 64
#define GHD 512
#define GM (GB*GN)          // 131072 flattened rows

// ---------------- scratch (device globals; no allocation allowed) ----------
__device__ float g_q[(size_t)GM * GHD];
__device__ float g_k[(size_t)GM * GHD];
__device__ float g_v[(size_t)GM * GHD];

// activation bf16 hi/lo planes: [2 tensors][M][256]
__device__ unsigned short g_Ahi[(size_t)2 * GM * GC];
__device__ unsigned short g_Alo[(size_t)2 * GM * GC];

// transposed + bf16-split weights: [3][N=512][K=256]
__device__ unsigned short g_WhiT[3 * GHD * GC];
__device__ unsigned short g_WloT[3 * GHD * GC];

#define CHUNKS 64
#define LCHUNK (GN / CHUNKS)              // 256
// per (chunk, b*h): 4096 kv + 64 ksum + 64 vsum = 4224 floats
__device__ float g_kvpart[(size_t)CHUNKS * 64 * 4224];
__device__ float g_kvred[(size_t)64 * 4224];

// ======================= helpers ===========================================
__device__ __forceinline__ uint32_t smem_to_u32(const void* p) {
    uint32_t a;
    asm("{ .reg .u64 t; cvta.to.shared.u64 t, %1; cvt.u32.u64 %0, t; }" : "=r"(a) : "l"(p));
    return a;
}
#define CP_ASYNC16(dst, src) \
    asm volatile("cp.async.cg.shared.global [%0], [%1], 16;" :: "r"(dst), "l"(src))
#define CP_COMMIT() asm volatile("cp.async.commit_group;" ::: "memory")
#define CP_WAIT(n)  asm volatile("cp.async.wait_group %0;" :: "n"(n) : "memory")

__device__ __forceinline__ uint32_t lds32(uint32_t a) {
    uint32_t v;
    asm volatile("ld.shared.b32 %0, [%1];" : "=r"(v) : "r"(a));
    return v;
}
__device__ __forceinline__ void mma16816(float* c, uint32_t a0, uint32_t a1,
                                         uint32_t a2, uint32_t a3,
                                         uint32_t b0, uint32_t b1) {
    asm volatile(
        "mma.sync.aligned.m16n8k16.row.col.f32.bf16.bf16.f32 "
        "{%0,%1,%2,%3}, {%4,%5,%6,%7}, {%8,%9}, {%0,%1,%2,%3};"
        : "+f"(c[0]), "+f"(c[1]), "+f"(c[2]), "+f"(c[3])
        : "r"(a0), "r"(a1), "r"(a2), "r"(a3), "r"(b0), "r"(b1));
}

// ================= weight prep: transpose + bf16 hi/lo split ===============
__global__ void prep_weights(const float* __restrict__ w0, const float* __restrict__ w1,
                             const float* __restrict__ w2)
{
    int m = blockIdx.x >> 9;          // 0..2
    int n = blockIdx.x & 511;         // 0..511
    int k = threadIdx.x;              // 0..255
    const float* W = (m == 0) ? w0 : (m == 1) ? w1 : w2;
    float x = W[(size_t)k * GHD + n];
    __nv_bfloat16 h = __float2bfloat16_rn(x);
    float r = x - __bfloat162float(h);
    __nv_bfloat16 l = __float2bfloat16_rn(r);
    size_t o = (size_t)m * GHD * GC + (size_t)n * GC + k;
    g_WhiT[o] = __bfloat16_as_ushort(h);
    g_WloT[o] = __bfloat16_as_ushort(l);
}

// ================= activation prep: bf16 hi/lo split =======================
// grid (8192, 2), 256 threads; each thread converts 4 float4 groups
__global__ void prep_act(const float* __restrict__ qin, const float* __restrict__ sin)
{
    const float* src = blockIdx.y ? sin : qin;
    unsigned short* dhi = g_Ahi + (size_t)blockIdx.y * GM * GC;
    unsigned short* dlo = g_Alo + (size_t)blockIdx.y * GM * GC;
    const size_t NF4 = (size_t)GM * GC / 4;   // 8388608
#pragma unroll
    for (int j = 0; j < 4; j++) {
        size_t i = (size_t)j * 2097152 + (size_t)blockIdx.x * 256 + threadIdx.x;
        if (i >= NF4) break;
        float4 x = ((const float4*)src)[i];
        float xs[4] = {x.x, x.y, x.z, x.w};
        unsigned short hs[4], ls[4];
#pragma unroll
        for (int e = 0; e < 4; e++) {
            __nv_bfloat16 h = __float2bfloat16_rn(xs[e]);
            __nv_bfloat16 l = __float2bfloat16_rn(xs[e] - __bfloat162float(h));
            hs[e] = __bfloat16_as_ushort(h);
            ls[e] = __bfloat16_as_ushort(l);
        }
        uint2 hp = {(uint32_t)hs[0] | ((uint32_t)hs[1] << 16),
                    (uint32_t)hs[2] | ((uint32_t)hs[3] << 16)};
        uint2 lp = {(uint32_t)ls[0] | ((uint32_t)ls[1] << 16),
                    (uint32_t)ls[2] | ((uint32_t)ls[3] << 16)};
        *(uint2*)&dhi[i * 4] = hp;
        *(uint2*)&dlo[i * 4] = lp;
    }
}

// ============== bf16x3 mma.sync GEMM: out[M,512]=A[M,256]@W^T+bias =========
// block tile 128(M) x 128(N), K chunks of 32, 2-stage cp.async pipeline.
// smem per plane per stage: 128 rows x 80B (64B data + 16B pad, conflict-free)
#define RS 80
#define PLANE_B (128 * RS)        // 10240
#define STAGE_B (4 * PLANE_B)     // 40960
#define GEMM_SMEM (2 * STAGE_B)   // 81920

__global__ __launch_bounds__(256, 1)
void gemm_mma(const unsigned short* __restrict__ Ahi, const unsigned short* __restrict__ Alo,
              const unsigned short* __restrict__ Bhi, const unsigned short* __restrict__ Blo,
              const float* __restrict__ bias, float* __restrict__ out)
{
    extern __shared__ char smem[];
    const uint32_t sb = smem_to_u32(smem);
    const int tid = threadIdx.x;
    const int lane = tid & 31, wid = tid >> 5;
    const int warpM = wid & 1;        // 2 warps in M
    const int warpN = wid >> 1;       // 4 warps in N
    const int lr = lane >> 2, lc = lane & 3;
    const int ntile = blockIdx.x;     // 0..3
    const int mtile = blockIdx.y;     // 0..1023

    // global plane base pointers (bytes), row stride 512B (K=256 bf16)
    const char* pAhi = (const char*)Ahi + (size_t)mtile * 128 * 512;
    const char* pAlo = (const char*)Alo + (size_t)mtile * 128 * 512;
    const char* pBhi = (const char*)Bhi + (size_t)ntile * 128 * 512;
    const char* pBlo = (const char*)Blo + (size_t)ntile * 128 * 512;

    float acc[4][4][4];
#pragma unroll
    for (int i = 0; i < 4; i++)
#pragma unroll
        for (int j = 0; j < 4; j++)
#pragma unroll
            for (int e = 0; e < 4; e++) acc[i][j][e] = 0.f;

    // ---- async chunk loader: chunk c (32 k-elems = 64B/row) into stage s --
    auto load_chunk = [&](int c, int s) {
        uint32_t sbase = sb + s * STAGE_B;
#pragma unroll
        for (int p = 0; p < 8; p++) {
            int plane = p >> 1;                       // 0:Ahi 1:Alo 2:Bhi 3:Blo
            int w = ((p & 1) << 8) + tid;             // 0..511
            int row = w >> 2, s4 = w & 3;
            uint32_t soff = sbase + plane * PLANE_B + row * RS + s4 * 16;
            const char* bp = (plane == 0) ? pAhi : (plane == 1) ? pAlo
                           : (plane == 2) ? pBhi : pBlo;
            const char* src = bp + (size_t)row * 512 + c * 64 + s4 * 16;
            CP_ASYNC16(soff, src);
        }
        CP_COMMIT();
    };

    load_chunk(0, 0);

    const int NCH = GC / 32;    // 8
    for (int c = 0; c < NCH; c++) {
        int s = c & 1;
        if (c + 1 < NCH) {
            load_chunk(c + 1, (c + 1) & 1);
            CP_WAIT(1);
        } else {
            CP_WAIT(0);
        }
        __syncthreads();

        uint32_t stb = sb + s * STAGE_B;
#pragma unroll
        for (int ks = 0; ks < 2; ks++) {
            uint32_t ah[4][4], al[4][4], bh[4][2], bl[4][2];
            uint32_t a0 = stb + (warpM * 64 + lr) * RS + lc * 4 + ks * 32;
#pragma unroll
            for (int mt = 0; mt < 4; mt++) {
                uint32_t o = a0 + mt * 16 * RS;
                ah[mt][0] = lds32(o);
                ah[mt][1] = lds32(o + 8 * RS);
                ah[mt][2] = lds32(o + 16);
                ah[mt][3] = lds32(o + 8 * RS + 16);
                al[mt][0] = lds32(o + PLANE_B);
                al[mt][1] = lds32(o + PLANE_B + 8 * RS);
                al[mt][2] = lds32(o + PLANE_B + 16);
                al[mt][3] = lds32(o + PLANE_B + 8 * RS + 16);
            }
            uint32_t b0 = stb + 2 * PLANE_B + (warpN * 32 + lr) * RS + lc * 4 + ks * 32;
#pragma unroll
            for (int nt = 0; nt < 4; nt++) {
                uint32_t o = b0 + nt * 8 * RS;
                bh[nt][0] = lds32(o);
                bh[nt][1] = lds32(o + 16);
                bl[nt][0] = lds32(o + PLANE_B);
                bl[nt][1] = lds32(o + PLANE_B + 16);
            }
            // pass 1: hi*hi
#pragma unroll
            for (int mt = 0; mt < 4; mt++)
#pragma unroll
                for (int nt = 0; nt < 4; nt++)
                    mma16816(acc[mt][nt], ah[mt][0], ah[mt][1], ah[mt][2], ah[mt][3],
                             bh[nt][0], bh[nt][1]);
            // pass 2: hi*lo
#pragma unroll
            for (int mt = 0; mt < 4; mt++)
#pragma unroll
                for (int nt = 0; nt < 4; nt++)
                    mma16816(acc[mt][nt], ah[mt][0], ah[mt][1], ah[mt][2], ah[mt][3],
                             bl[nt][0], bl[nt][1]);
            // pass 3: lo*hi
#pragma unroll
            for (int mt = 0; mt < 4; mt++)
#pragma unroll
                for (int nt = 0; nt < 4; nt++)
                    mma16816(acc[mt][nt], al[mt][0], al[mt][1], al[mt][2], al[mt][3],
                             bh[nt][0], bh[nt][1]);
        }
        __syncthreads();
    }

    // epilogue: bias + store
#pragma unroll
    for (int mt = 0; mt < 4; mt++) {
        int gm = mtile * 128 + warpM * 64 + mt * 16 + lr;
#pragma unroll
        for (int nt = 0; nt < 4; nt++) {
            int gn = ntile * 128 + warpN * 32 + nt * 8 + lc * 2;
            float2 bb = *(const float2*)&bias[gn];
            float2 o0, o1;
            o0.x = acc[mt][nt][0] + bb.x;
            o0.y = acc[mt][nt][1] + bb.y;
            o1.x = acc[mt][nt][2] + bb.x;
            o1.y = acc[mt][nt][3] + bb.y;
            *(float2*)&out[(size_t)gm * GHD + gn]       = o0;
            *(float2*)&out[(size_t)(gm + 8) * GHD + gn] = o1;
        }
    }
}

// ---------------- reduce stage 1: partial kv / ksum / vsum -----------------
#define RROWS 16

__global__ __launch_bounds__(256) void reduce_stage1(void)
{
    int chunk = blockIdx.x;
    int bh    = blockIdx.y;
    int b = bh >> 3, h = bh & 7;

    __shared__ float sk[RROWS][64];
    __shared__ float sv[RROWS][64];

    int tid  = threadIdx.x;
    int m    = tid & 63;
    int dg   = tid >> 6;
    int lane = tid & 31, warp = tid >> 5;
    int ldr = tid >> 4, ldc = (tid & 15) * 4;   // load row 0..15, col

    const float* kbase = g_k + (size_t)b * GN * GHD + h * GD;
    const float* vbase = g_v + (size_t)b * GN * GHD + h * GD;

    float acc[16];
#pragma unroll
    for (int j = 0; j < 16; j++) acc[j] = 0.f;
    float sacc = 0.f;

    int lend = (chunk + 1) * LCHUNK;
    for (int l0 = chunk * LCHUNK; l0 < lend; l0 += RROWS) {
        *(float4*)&sk[ldr][ldc] = *(const float4*)&kbase[(size_t)(l0 + ldr) * GHD + ldc];
        *(float4*)&sv[ldr][ldc] = *(const float4*)&vbase[(size_t)(l0 + ldr) * GHD + ldc];
        __syncthreads();
        // normalize: warp w handles rows 2w, 2w+1
#pragma unroll
        for (int rr = 0; rr < 2; rr++) {
            int r = warp * 2 + rr;
            float x0 = sk[r][lane], x1 = sk[r][lane + 32];
            float ss = x0 * x0 + x1 * x1;
#pragma unroll
            for (int o = 16; o > 0; o >>= 1)
                ss += __shfl_xor_sync(0xffffffffu, ss, o);
            float inv = rsqrtf(ss);
            sk[r][lane]      = x0 * inv;
            sk[r][lane + 32] = x1 * inv;
        }
        __syncthreads();
#pragma unroll
        for (int r = 0; r < RROWS; r++) {
            float kval = sk[r][m];
            float4 v0 = *(const float4*)&sv[r][dg * 16 + 0];
            float4 v1 = *(const float4*)&sv[r][dg * 16 + 4];
            float4 v2 = *(const float4*)&sv[r][dg * 16 + 8];
            float4 v3 = *(const float4*)&sv[r][dg * 16 + 12];
            acc[0]  += kval * v0.x; acc[1]  += kval * v0.y;
            acc[2]  += kval * v0.z; acc[3]  += kval * v0.w;
            acc[4]  += kval * v1.x; acc[5]  += kval * v1.y;
            acc[6]  += kval * v1.z; acc[7]  += kval * v1.w;
            acc[8]  += kval * v2.x; acc[9]  += kval * v2.y;
            acc[10] += kval * v2.z; acc[11] += kval * v2.w;
            acc[12] += kval * v3.x; acc[13] += kval * v3.y;
            acc[14] += kval * v3.z; acc[15] += kval * v3.w;
            if (dg == 0)      sacc += kval;
            else if (dg == 1) sacc += sv[r][m];
        }
        __syncthreads();
    }

    float* dst = g_kvpart + ((size_t)chunk * 64 + bh) * 4224;
#pragma unroll
    for (int j = 0; j < 16; j++) dst[m * 64 + dg * 16 + j] = acc[j];
    if (dg == 0)      dst[4096 + m] = sacc;
    else if (dg == 1) dst[4160 + m] = sacc;
}

// ---------------- reduce stage 2 -------------------------------------------
__global__ void reduce_stage2(void)
{
    int i = blockIdx.x * blockDim.x + threadIdx.x;
    if (i >= 64 * 4224) return;
    float s = 0.f;
#pragma unroll 8
    for (int c = 0; c < CHUNKS; c++)
        s += g_kvpart[(size_t)c * 64 * 4224 + i];
    g_kvred[i] = s;
}

// ---------------- final ----------------------------------------------------
#define FROWS 64

__global__ __launch_bounds__(256) void final_kernel(float* __restrict__ out)
{
    __shared__ float sq[FROWS][GD];
    __shared__ float skv[GD][GD];
    __shared__ float sksum[GD];
    __shared__ float svsum[GD];
    __shared__ float sden[FROWS];

    int tid  = threadIdx.x;
    int dq   = tid & 15;
    int rg   = tid >> 4;
    int lane = tid & 31, warp = tid >> 5;

    size_t row0 = (size_t)blockIdx.x * FROWS;
    int b = (int)(row0 / GN);
    const float* qbase = g_q + row0 * GHD;
    const float Nf = (float)GN;

    float outacc[4][4];
#pragma unroll
    for (int i = 0; i < 4; i++)
#pragma unroll
        for (int j = 0; j < 4; j++) outacc[i][j] = 0.f;

    for (int h = 0; h < GH; h++) {
        const float* kvb = g_kvred + (size_t)(b * GH + h) * 4224;
#pragma unroll
        for (int t = 0; t < 4; t++)
            ((float4*)skv)[tid + t * 256] = ((const float4*)kvb)[tid + t * 256];
        if (tid < 64)        sksum[tid]      = kvb[4096 + tid];
        else if (tid < 128)  svsum[tid - 64] = kvb[4096 + tid];
#pragma unroll
        for (int t = 0; t < 16; t++) {
            int idx = tid + t * 256;
            int r = idx >> 6, c = idx & 63;
            sq[r][c] = qbase[(size_t)r * GHD + h * GD + c];
        }
        __syncthreads();

#pragma unroll
        for (int rr = 0; rr < 8; rr++) {
            int r = warp * 8 + rr;
            float x0 = sq[r][lane], x1 = sq[r][lane + 32];
            float ss = x0 * x0 + x1 * x1;
#pragma unroll
            for (int o = 16; o > 0; o >>= 1)
                ss += __shfl_xor_sync(0xffffffffu, ss, o);
            float inv = rsqrtf(ss);
            sq[r][lane]      = x0 * inv;
            sq[r][lane + 32] = x1 * inv;
        }
        __syncthreads();

#pragma unroll
        for (int rr = 0; rr < 8; rr++) {
            int r = warp * 8 + rr;
            float p = sq[r][lane] * sksum[lane] + sq[r][lane + 32] * sksum[lane + 32];
#pragma unroll
            for (int o = 16; o > 0; o >>= 1)
                p += __shfl_xor_sync(0xffffffffu, p, o);
            if (lane == 0) sden[r] = p + 2.f * Nf;
        }
        __syncthreads();

        float a[4][4];
#pragma unroll
        for (int i = 0; i < 4; i++)
#pragma unroll
            for (int j = 0; j < 4; j++) a[i][j] = 0.f;

        for (int m = 0; m < GD; m++) {
            float4 kvv = *(const float4*)&skv[m][dq * 4];
#pragma unroll
            for (int i = 0; i < 4; i++) {
                float qv = sq[rg * 4 + i][m];
                a[i][0] += qv * kvv.x;
                a[i][1] += qv * kvv.y;
                a[i][2] += qv * kvv.z;
                a[i][3] += qv * kvv.w;
            }
        }
        float4 vsv = *(const float4*)&svsum[dq * 4];
#pragma unroll
        for (int i = 0; i < 4; i++) {
            float rden = 1.f / sden[rg * 4 + i];
            outacc[i][0] += (a[i][0] + Nf * vsv.x) * rden;
            outacc[i][1] += (a[i][1] + Nf * vsv.y) * rden;
            outacc[i][2] += (a[i][2] + Nf * vsv.z) * rden;
            outacc[i][3] += (a[i][3] + Nf * vsv.w) * rden;
        }
        __syncthreads();
    }

#pragma unroll
    for (int i = 0; i < 4; i++) {
        float4 o;
        o.x = outacc[i][0] * (1.f / GH);
        o.y = outacc[i][1] * (1.f / GH);
        o.z = outacc[i][2] * (1.f / GH);
        o.w = outacc[i][3] * (1.f / GH);
        *(float4*)(out + (row0 + rg * 4 + i) * GD + dq * 4) = o;
    }
}

// ---------------- launch ---------------------------------------------------
extern "C" void kernel_launch(void* const* d_in, const int* in_sizes, int n_in,
                              void* d_out, int out_size)
{
    const float* q_in = (const float*)d_in[0];
    const float* s_in = (const float*)d_in[1];
    const float* Wq   = (const float*)d_in[2];
    const float* bq   = (const float*)d_in[3];
    const float* Wk   = (const float*)d_in[4];
    const float* bk   = (const float*)d_in[5];
    const float* Wv   = (const float*)d_in[6];
    const float* bv   = (const float*)d_in[7];
    float* out = (float*)d_out;

    float *gq, *gk, *gv;
    unsigned short *ahi, *alo, *whi, *wlo;
    cudaGetSymbolAddress((void**)&gq, g_q);
    cudaGetSymbolAddress((void**)&gk, g_k);
    cudaGetSymbolAddress((void**)&gv, g_v);
    cudaGetSymbolAddress((void**)&ahi, g_Ahi);
    cudaGetSymbolAddress((void**)&alo, g_Alo);
    cudaGetSymbolAddress((void**)&whi, g_WhiT);
    cudaGetSymbolAddress((void**)&wlo, g_WloT);

    static int smem_set = 0;
    if (!smem_set) {
        cudaFuncSetAttribute(gemm_mma, cudaFuncAttributeMaxDynamicSharedMemorySize, GEMM_SMEM);
        smem_set = 1;
    }

    prep_weights<<<3 * GHD, 256>>>(Wq, Wk, Wv);
    prep_act<<<dim3(8192, 2), 256>>>(q_in, s_in);

    const size_t TA = (size_t)GM * GC;     // per-tensor activation plane size
    const size_t TW = (size_t)GHD * GC;    // per-matrix weight plane size
    dim3 ggrid(GHD / 128, GM / 128);       // (4, 1024): ntile fastest for A reuse
    gemm_mma<<<ggrid, 256, GEMM_SMEM>>>(ahi,      alo,      whi,          wlo,          bq, gq);
    gemm_mma<<<ggrid, 256, GEMM_SMEM>>>(ahi + TA, alo + TA, whi + TW,     wlo + TW,     bk, gk);
    gemm_mma<<<ggrid, 256, GEMM_SMEM>>>(ahi + TA, alo + TA, whi + 2 * TW, wlo + 2 * TW, bv, gv);

    reduce_stage1<<<dim3(CHUNKS, 64), 256>>>();
    reduce_stage2<<<(64 * 4224 + 255) / 256, 256>>>();

    final_kernel<<<GM / FROWS, 256>>>(out);
}

// round 6
// speedup vs baseline: 1.6770x; 1.0333x over previous
#include <cuda_runtime.h>
#include <cuda_bf16.h>
#include <cstdint>

// Problem constants
#define GB 8
#define GN 16384
#define GC 256
#define GH 8
#define GD 64
#define GHD 512
#define GM (GB*GN)          // 131072 flattened rows

// ---------------- scratch (device globals; no allocation allowed) ----------
__device__ float g_q[(size_t)GM * GHD];
__device__ float g_k[(size_t)GM * GHD];
__device__ float g_v[(size_t)GM * GHD];

// activation bf16 hi/lo planes: [2 tensors][M][256]
__device__ unsigned short g_Ahi[(size_t)2 * GM * GC];
__device__ unsigned short g_Alo[(size_t)2 * GM * GC];

// transposed + bf16-split weights: [3][N=512][K=256]
__device__ unsigned short g_WhiT[3 * GHD * GC];
__device__ unsigned short g_WloT[3 * GHD * GC];

#define CHUNKS 64
#define LCHUNK (GN / CHUNKS)              // 256
// per (chunk, b*h): 4096 kv + 64 ksum + 64 vsum = 4224 floats
__device__ float g_kvpart[(size_t)CHUNKS * 64 * 4224];
__device__ float g_kvred[(size_t)64 * 4224];

// ======================= helpers ===========================================
__device__ __forceinline__ uint32_t smem_to_u32(const void* p) {
    uint32_t a;
    asm("{ .reg .u64 t; cvta.to.shared.u64 t, %1; cvt.u32.u64 %0, t; }" : "=r"(a) : "l"(p));
    return a;
}
#define CP_ASYNC16(dst, src) \
    asm volatile("cp.async.cg.shared.global [%0], [%1], 16;" :: "r"(dst), "l"(src))
#define CP_COMMIT() asm volatile("cp.async.commit_group;" ::: "memory")
#define CP_WAIT(n)  asm volatile("cp.async.wait_group %0;" :: "n"(n) : "memory")

__device__ __forceinline__ uint32_t lds32(uint32_t a) {
    uint32_t v;
    asm volatile("ld.shared.b32 %0, [%1];" : "=r"(v) : "r"(a));
    return v;
}
__device__ __forceinline__ void mma16816(float* c, uint32_t a0, uint32_t a1,
                                         uint32_t a2, uint32_t a3,
                                         uint32_t b0, uint32_t b1) {
    asm volatile(
        "mma.sync.aligned.m16n8k16.row.col.f32.bf16.bf16.f32 "
        "{%0,%1,%2,%3}, {%4,%5,%6,%7}, {%8,%9}, {%0,%1,%2,%3};"
        : "+f"(c[0]), "+f"(c[1]), "+f"(c[2]), "+f"(c[3])
        : "r"(a0), "r"(a1), "r"(a2), "r"(a3), "r"(b0), "r"(b1));
}

// ================= weight prep: transpose + bf16 hi/lo split ===============
__global__ void prep_weights(const float* __restrict__ w0, const float* __restrict__ w1,
                             const float* __restrict__ w2)
{
    int m = blockIdx.x >> 9;          // 0..2
    int n = blockIdx.x & 511;         // 0..511
    int k = threadIdx.x;              // 0..255
    const float* W = (m == 0) ? w0 : (m == 1) ? w1 : w2;
    float x = W[(size_t)k * GHD + n];
    __nv_bfloat16 h = __float2bfloat16_rn(x);
    float r = x - __bfloat162float(h);
    __nv_bfloat16 l = __float2bfloat16_rn(r);
    size_t o = (size_t)m * GHD * GC + (size_t)n * GC + k;
    g_WhiT[o] = __bfloat16_as_ushort(h);
    g_WloT[o] = __bfloat16_as_ushort(l);
}

// ================= activation prep: bf16 hi/lo split =======================
__global__ void prep_act(const float* __restrict__ qin, const float* __restrict__ sin)
{
    const float* src = blockIdx.y ? sin : qin;
    unsigned short* dhi = g_Ahi + (size_t)blockIdx.y * GM * GC;
    unsigned short* dlo = g_Alo + (size_t)blockIdx.y * GM * GC;
    const size_t NF4 = (size_t)GM * GC / 4;   // 8388608
#pragma unroll
    for (int j = 0; j < 4; j++) {
        size_t i = (size_t)j * 2097152 + (size_t)blockIdx.x * 256 + threadIdx.x;
        if (i >= NF4) break;
        float4 x = ((const float4*)src)[i];
        float xs[4] = {x.x, x.y, x.z, x.w};
        unsigned short hs[4], ls[4];
#pragma unroll
        for (int e = 0; e < 4; e++) {
            __nv_bfloat16 h = __float2bfloat16_rn(xs[e]);
            __nv_bfloat16 l = __float2bfloat16_rn(xs[e] - __bfloat162float(h));
            hs[e] = __bfloat16_as_ushort(h);
            ls[e] = __bfloat16_as_ushort(l);
        }
        uint2 hp = {(uint32_t)hs[0] | ((uint32_t)hs[1] << 16),
                    (uint32_t)hs[2] | ((uint32_t)hs[3] << 16)};
        uint2 lp = {(uint32_t)ls[0] | ((uint32_t)ls[1] << 16),
                    (uint32_t)ls[2] | ((uint32_t)ls[3] << 16)};
        *(uint2*)&dhi[i * 4] = hp;
        *(uint2*)&dlo[i * 4] = lp;
    }
}

// ============== bf16x3 mma.sync GEMM: out[M,512]=A[M,256]@W^T+bias =========
// block tile 64(M) x 128(N), K chunks of 32, 3-stage cp.async pipeline,
// 2 CTAs/SM. smem rows 80B stride (64B data + 16B pad, conflict-free).
#define RS 80
#define PLANE_A (64 * RS)          // 5120
#define PLANE_B2 (128 * RS)        // 10240
#define OFF_ALO PLANE_A
#define OFF_BHI (2 * PLANE_A)
#define OFF_BLO (2 * PLANE_A + PLANE_B2)
#define STAGE_B (2 * PLANE_A + 2 * PLANE_B2)   // 30720
#define NSTAGE 3
#define GEMM_SMEM (NSTAGE * STAGE_B)           // 92160

__global__ __launch_bounds__(256, 2)
void gemm_mma(const unsigned short* __restrict__ Ahi, const unsigned short* __restrict__ Alo,
              const unsigned short* __restrict__ Bhi, const unsigned short* __restrict__ Blo,
              const float* __restrict__ bias, float* __restrict__ out)
{
    extern __shared__ char smem[];
    const uint32_t sb = smem_to_u32(smem);
    const int tid = threadIdx.x;
    const int lane = tid & 31, wid = tid >> 5;
    const int warpM = wid & 1;        // 2 warps in M (32 rows each)
    const int warpN = wid >> 1;       // 4 warps in N (32 cols each)
    const int lr = lane >> 2, lc = lane & 3;
    const int ntile = blockIdx.x;     // 0..3
    const int mtile = blockIdx.y;     // 0..2047

    // global plane base pointers (bytes), row stride 512B (K=256 bf16)
    const char* pAhi = (const char*)Ahi + (size_t)mtile * 64 * 512;
    const char* pAlo = (const char*)Alo + (size_t)mtile * 64 * 512;
    const char* pBhi = (const char*)Bhi + (size_t)ntile * 128 * 512;
    const char* pBlo = (const char*)Blo + (size_t)ntile * 128 * 512;

    float acc[2][4][4];
#pragma unroll
    for (int i = 0; i < 2; i++)
#pragma unroll
        for (int j = 0; j < 4; j++)
#pragma unroll
            for (int e = 0; e < 4; e++) acc[i][j][e] = 0.f;

    // ---- async chunk loader: chunk c (32 k = 64B/row) into stage s --------
    auto load_chunk = [&](int c, int s) {
        uint32_t sbase = sb + s * STAGE_B;
        // A planes: 64 rows x 4 segs = 256 cp per plane (1/thread)
        {
            int row = tid >> 2, s4 = tid & 3;
            uint32_t so = sbase + row * RS + s4 * 16;
            size_t go = (size_t)row * 512 + c * 64 + s4 * 16;
            CP_ASYNC16(so, pAhi + go);
            CP_ASYNC16(so + OFF_ALO, pAlo + go);
        }
        // B planes: 128 rows x 4 segs = 512 cp per plane (2/thread)
#pragma unroll
        for (int t = 0; t < 2; t++) {
            int w = tid + t * 256;
            int row = w >> 2, s4 = w & 3;
            uint32_t so = sbase + OFF_BHI + row * RS + s4 * 16;
            size_t go = (size_t)row * 512 + c * 64 + s4 * 16;
            CP_ASYNC16(so, pBhi + go);
            CP_ASYNC16(so + PLANE_B2, pBlo + go);
        }
        CP_COMMIT();
    };

    const int NCH = GC / 32;    // 8
    load_chunk(0, 0);
    load_chunk(1, 1);

    for (int c = 0; c < NCH; c++) {
        if (c + 2 < NCH) { load_chunk(c + 2, (c + 2) % NSTAGE); CP_WAIT(2); }
        else if (c + 1 < NCH) CP_WAIT(1);
        else CP_WAIT(0);
        __syncthreads();

        uint32_t stb = sb + (c % NSTAGE) * STAGE_B;
#pragma unroll
        for (int ks = 0; ks < 2; ks++) {
            uint32_t ah[2][4], al[2][4], bh[4][2], bl[4][2];
            uint32_t a0 = stb + (warpM * 32 + lr) * RS + lc * 4 + ks * 32;
#pragma unroll
            for (int mt = 0; mt < 2; mt++) {
                uint32_t o = a0 + mt * 16 * RS;
                ah[mt][0] = lds32(o);
                ah[mt][1] = lds32(o + 8 * RS);
                ah[mt][2] = lds32(o + 16);
                ah[mt][3] = lds32(o + 8 * RS + 16);
                al[mt][0] = lds32(o + OFF_ALO);
                al[mt][1] = lds32(o + OFF_ALO + 8 * RS);
                al[mt][2] = lds32(o + OFF_ALO + 16);
                al[mt][3] = lds32(o + OFF_ALO + 8 * RS + 16);
            }
            uint32_t b0 = stb + OFF_BHI + (warpN * 32 + lr) * RS + lc * 4 + ks * 32;
#pragma unroll
            for (int nt = 0; nt < 4; nt++) {
                uint32_t o = b0 + nt * 8 * RS;
                bh[nt][0] = lds32(o);
                bh[nt][1] = lds32(o + 16);
                bl[nt][0] = lds32(o + PLANE_B2);
                bl[nt][1] = lds32(o + PLANE_B2 + 16);
            }
#pragma unroll
            for (int mt = 0; mt < 2; mt++)
#pragma unroll
                for (int nt = 0; nt < 4; nt++)
                    mma16816(acc[mt][nt], ah[mt][0], ah[mt][1], ah[mt][2], ah[mt][3],
                             bh[nt][0], bh[nt][1]);
#pragma unroll
            for (int mt = 0; mt < 2; mt++)
#pragma unroll
                for (int nt = 0; nt < 4; nt++)
                    mma16816(acc[mt][nt], ah[mt][0], ah[mt][1], ah[mt][2], ah[mt][3],
                             bl[nt][0], bl[nt][1]);
#pragma unroll
            for (int mt = 0; mt < 2; mt++)
#pragma unroll
                for (int nt = 0; nt < 4; nt++)
                    mma16816(acc[mt][nt], al[mt][0], al[mt][1], al[mt][2], al[mt][3],
                             bh[nt][0], bh[nt][1]);
        }
        __syncthreads();
    }

    // epilogue: bias + store
#pragma unroll
    for (int mt = 0; mt < 2; mt++) {
        int gm = mtile * 64 + warpM * 32 + mt * 16 + lr;
#pragma unroll
        for (int nt = 0; nt < 4; nt++) {
            int gn = ntile * 128 + warpN * 32 + nt * 8 + lc * 2;
            float2 bb = *(const float2*)&bias[gn];
            float2 o0, o1;
            o0.x = acc[mt][nt][0] + bb.x;
            o0.y = acc[mt][nt][1] + bb.y;
            o1.x = acc[mt][nt][2] + bb.x;
            o1.y = acc[mt][nt][3] + bb.y;
            *(float2*)&out[(size_t)gm * GHD + gn]       = o0;
            *(float2*)&out[(size_t)(gm + 8) * GHD + gn] = o1;
        }
    }
}

// ---------------- reduce stage 1: partial kv / ksum / vsum -----------------
#define RROWS 16

__global__ __launch_bounds__(256) void reduce_stage1(void)
{
    int chunk = blockIdx.x;
    int bh    = blockIdx.y;
    int b = bh >> 3, h = bh & 7;

    __shared__ float sk[RROWS][64];
    __shared__ float sv[RROWS][64];

    int tid  = threadIdx.x;
    int m    = tid & 63;
    int dg   = tid >> 6;
    int lane = tid & 31, warp = tid >> 5;
    int ldr = tid >> 4, ldc = (tid & 15) * 4;

    const float* kbase = g_k + (size_t)b * GN * GHD + h * GD;
    const float* vbase = g_v + (size_t)b * GN * GHD + h * GD;

    float acc[16];
#pragma unroll
    for (int j = 0; j < 16; j++) acc[j] = 0.f;
    float sacc = 0.f;

    int lend = (chunk + 1) * LCHUNK;
    for (int l0 = chunk * LCHUNK; l0 < lend; l0 += RROWS) {
        *(float4*)&sk[ldr][ldc] = *(const float4*)&kbase[(size_t)(l0 + ldr) * GHD + ldc];
        *(float4*)&sv[ldr][ldc] = *(const float4*)&vbase[(size_t)(l0 + ldr) * GHD + ldc];
        __syncthreads();
#pragma unroll
        for (int rr = 0; rr < 2; rr++) {
            int r = warp * 2 + rr;
            float x0 = sk[r][lane], x1 = sk[r][lane + 32];
            float ss = x0 * x0 + x1 * x1;
#pragma unroll
            for (int o = 16; o > 0; o >>= 1)
                ss += __shfl_xor_sync(0xffffffffu, ss, o);
            float inv = rsqrtf(ss);
            sk[r][lane]      = x0 * inv;
            sk[r][lane + 32] = x1 * inv;
        }
        __syncthreads();
#pragma unroll
        for (int r = 0; r < RROWS; r++) {
            float kval = sk[r][m];
            float4 v0 = *(const float4*)&sv[r][dg * 16 + 0];
            float4 v1 = *(const float4*)&sv[r][dg * 16 + 4];
            float4 v2 = *(const float4*)&sv[r][dg * 16 + 8];
            float4 v3 = *(const float4*)&sv[r][dg * 16 + 12];
            acc[0]  += kval * v0.x; acc[1]  += kval * v0.y;
            acc[2]  += kval * v0.z; acc[3]  += kval * v0.w;
            acc[4]  += kval * v1.x; acc[5]  += kval * v1.y;
            acc[6]  += kval * v1.z; acc[7]  += kval * v1.w;
            acc[8]  += kval * v2.x; acc[9]  += kval * v2.y;
            acc[10] += kval * v2.z; acc[11] += kval * v2.w;
            acc[12] += kval * v3.x; acc[13] += kval * v3.y;
            acc[14] += kval * v3.z; acc[15] += kval * v3.w;
            if (dg == 0)      sacc += kval;
            else if (dg == 1) sacc += sv[r][m];
        }
        __syncthreads();
    }

    float* dst = g_kvpart + ((size_t)chunk * 64 + bh) * 4224;
#pragma unroll
    for (int j = 0; j < 16; j++) dst[m * 64 + dg * 16 + j] = acc[j];
    if (dg == 0)      dst[4096 + m] = sacc;
    else if (dg == 1) dst[4160 + m] = sacc;
}

// ---------------- reduce stage 2 -------------------------------------------
__global__ void reduce_stage2(void)
{
    int i = blockIdx.x * blockDim.x + threadIdx.x;
    if (i >= 64 * 4224) return;
    float s = 0.f;
#pragma unroll 8
    for (int c = 0; c < CHUNKS; c++)
        s += g_kvpart[(size_t)c * 64 * 4224 + i];
    g_kvred[i] = s;
}

// ---------------- final ----------------------------------------------------
#define FROWS 64

__global__ __launch_bounds__(256) void final_kernel(float* __restrict__ out)
{
    __shared__ float sq[FROWS][GD];
    __shared__ float skv[GD][GD];
    __shared__ float sksum[GD];
    __shared__ float svsum[GD];
    __shared__ float sden[FROWS];

    int tid  = threadIdx.x;
    int dq   = tid & 15;
    int rg   = tid >> 4;
    int lane = tid & 31, warp = tid >> 5;

    size_t row0 = (size_t)blockIdx.x * FROWS;
    int b = (int)(row0 / GN);
    const float* qbase = g_q + row0 * GHD;
    const float Nf = (float)GN;

    float outacc[4][4];
#pragma unroll
    for (int i = 0; i < 4; i++)
#pragma unroll
        for (int j = 0; j < 4; j++) outacc[i][j] = 0.f;

    for (int h = 0; h < GH; h++) {
        const float* kvb = g_kvred + (size_t)(b * GH + h) * 4224;
#pragma unroll
        for (int t = 0; t < 4; t++)
            ((float4*)skv)[tid + t * 256] = ((const float4*)kvb)[tid + t * 256];
        if (tid < 64)        sksum[tid]      = kvb[4096 + tid];
        else if (tid < 128)  svsum[tid - 64] = kvb[4096 + tid];
#pragma unroll
        for (int t = 0; t < 16; t++) {
            int idx = tid + t * 256;
            int r = idx >> 6, c = idx & 63;
            sq[r][c] = qbase[(size_t)r * GHD + h * GD + c];
        }
        __syncthreads();

#pragma unroll
        for (int rr = 0; rr < 8; rr++) {
            int r = warp * 8 + rr;
            float x0 = sq[r][lane], x1 = sq[r][lane + 32];
            float ss = x0 * x0 + x1 * x1;
#pragma unroll
            for (int o = 16; o > 0; o >>= 1)
                ss += __shfl_xor_sync(0xffffffffu, ss, o);
            float inv = rsqrtf(ss);
            sq[r][lane]      = x0 * inv;
            sq[r][lane + 32] = x1 * inv;
        }
        __syncthreads();

#pragma unroll
        for (int rr = 0; rr < 8; rr++) {
            int r = warp * 8 + rr;
            float p = sq[r][lane] * sksum[lane] + sq[r][lane + 32] * sksum[lane + 32];
#pragma unroll
            for (int o = 16; o > 0; o >>= 1)
                p += __shfl_xor_sync(0xffffffffu, p, o);
            if (lane == 0) sden[r] = p + 2.f * Nf;
        }
        __syncthreads();

        float a[4][4];
#pragma unroll
        for (int i = 0; i < 4; i++)
#pragma unroll
            for (int j = 0; j < 4; j++) a[i][j] = 0.f;

        for (int m = 0; m < GD; m++) {
            float4 kvv = *(const float4*)&skv[m][dq * 4];
#pragma unroll
            for (int i = 0; i < 4; i++) {
                float qv = sq[rg * 4 + i][m];
                a[i][0] += qv * kvv.x;
                a[i][1] += qv * kvv.y;
                a[i][2] += qv * kvv.z;
                a[i][3] += qv * kvv.w;
            }
        }
        float4 vsv = *(const float4*)&svsum[dq * 4];
#pragma unroll
        for (int i = 0; i < 4; i++) {
            float rden = 1.f / sden[rg * 4 + i];
            outacc[i][0] += (a[i][0] + Nf * vsv.x) * rden;
            outacc[i][1] += (a[i][1] + Nf * vsv.y) * rden;
            outacc[i][2] += (a[i][2] + Nf * vsv.z) * rden;
            outacc[i][3] += (a[i][3] + Nf * vsv.w) * rden;
        }
        __syncthreads();
    }

#pragma unroll
    for (int i = 0; i < 4; i++) {
        float4 o;
        o.x = outacc[i][0] * (1.f / GH);
        o.y = outacc[i][1] * (1.f / GH);
        o.z = outacc[i][2] * (1.f / GH);
        o.w = outacc[i][3] * (1.f / GH);
        *(float4*)(out + (row0 + rg * 4 + i) * GD + dq * 4) = o;
    }
}

// ---------------- launch ---------------------------------------------------
extern "C" void kernel_launch(void* const* d_in, const int* in_sizes, int n_in,
                              void* d_out, int out_size)
{
    const float* q_in = (const float*)d_in[0];
    const float* s_in = (const float*)d_in[1];
    const float* Wq   = (const float*)d_in[2];
    const float* bq   = (const float*)d_in[3];
    const float* Wk   = (const float*)d_in[4];
    const float* bk   = (const float*)d_in[5];
    const float* Wv   = (const float*)d_in[6];
    const float* bv   = (const float*)d_in[7];
    float* out = (float*)d_out;

    float *gq, *gk, *gv;
    unsigned short *ahi, *alo, *whi, *wlo;
    cudaGetSymbolAddress((void**)&gq, g_q);
    cudaGetSymbolAddress((void**)&gk, g_k);
    cudaGetSymbolAddress((void**)&gv, g_v);
    cudaGetSymbolAddress((void**)&ahi, g_Ahi);
    cudaGetSymbolAddress((void**)&alo, g_Alo);
    cudaGetSymbolAddress((void**)&whi, g_WhiT);
    cudaGetSymbolAddress((void**)&wlo, g_WloT);

    static cudaStream_t s2 = nullptr;
    static cudaEvent_t evFork = nullptr, evJoin = nullptr;
    if (s2 == nullptr) {
        cudaFuncSetAttribute(gemm_mma, cudaFuncAttributeMaxDynamicSharedMemorySize, GEMM_SMEM);
        cudaStreamCreateWithFlags(&s2, cudaStreamNonBlocking);
        cudaEventCreateWithFlags(&evFork, cudaEventDisableTiming);
        cudaEventCreateWithFlags(&evJoin, cudaEventDisableTiming);
    }

    prep_weights<<<3 * GHD, 256>>>(Wq, Wk, Wv);
    prep_act<<<dim3(8192, 2), 256>>>(q_in, s_in);

    const size_t TA = (size_t)GM * GC;     // per-tensor activation plane size
    const size_t TW = (size_t)GHD * GC;    // per-matrix weight plane size
    dim3 ggrid(GHD / 128, GM / 64);        // (4, 2048): ntile fastest for A reuse
    gemm_mma<<<ggrid, 256, GEMM_SMEM>>>(ahi + TA, alo + TA, whi + TW,     wlo + TW,     bk, gk);
    gemm_mma<<<ggrid, 256, GEMM_SMEM>>>(ahi + TA, alo + TA, whi + 2 * TW, wlo + 2 * TW, bv, gv);

    // fork: q-projection (tensor-bound) overlaps the kv reduction (mem-bound)
    cudaEventRecord(evFork, 0);
    cudaStreamWaitEvent(s2, evFork, 0);
    gemm_mma<<<ggrid, 256, GEMM_SMEM, s2>>>(ahi, alo, whi, wlo, bq, gq);

    reduce_stage1<<<dim3(CHUNKS, 64), 256>>>();
    reduce_stage2<<<(64 * 4224 + 255) / 256, 256>>>();

    cudaEventRecord(evJoin, s2);
    cudaStreamWaitEvent(0, evJoin, 0);

    final_kernel<<<GM / FROWS, 256>>>(out);
}

// round 9
// speedup vs baseline: 1.7709x; 1.0560x over previous
#include <cuda_runtime.h>
#include <cuda_bf16.h>
#include <cstdint>

// Problem constants
#define GB 8
#define GN 16384
#define GC 256
#define GH 8
#define GD 64
#define GHD 512
#define GM (GB*GN)          // 131072 flattened rows

// ---------------- scratch (device globals; no allocation allowed) ----------
__device__ float g_q[(size_t)GM * GHD];
__device__ float g_k[(size_t)GM * GHD];
__device__ float g_v[(size_t)GM * GHD];

// activation bf16 hi/lo planes: [2 tensors][M][256]
__device__ unsigned short g_Ahi[(size_t)2 * GM * GC];
__device__ unsigned short g_Alo[(size_t)2 * GM * GC];

// transposed + bf16-split weights: [3][N=512][K=256]
__device__ unsigned short g_WhiT[3 * GHD * GC];
__device__ unsigned short g_WloT[3 * GHD * GC];

#define CHUNKS 64
#define LCHUNK (GN / CHUNKS)              // 256
// per (chunk, b*h): 4096 kv + 64 ksum + 64 vsum = 4224 floats
__device__ float g_kvpart[(size_t)CHUNKS * 64 * 4224];
__device__ float g_kvred[(size_t)64 * 4224];

// ======================= helpers ===========================================
__device__ __forceinline__ uint32_t smem_to_u32(const void* p) {
    uint32_t a;
    asm("{ .reg .u64 t; cvta.to.shared.u64 t, %1; cvt.u32.u64 %0, t; }" : "=r"(a) : "l"(p));
    return a;
}
#define CP_ASYNC16(dst, src) \
    asm volatile("cp.async.cg.shared.global [%0], [%1], 16;" :: "r"(dst), "l"(src))
#define CP_COMMIT() asm volatile("cp.async.commit_group;" ::: "memory")
#define CP_WAIT(n)  asm volatile("cp.async.wait_group %0;" :: "n"(n) : "memory")

__device__ __forceinline__ uint32_t lds32(uint32_t a) {
    uint32_t v;
    asm volatile("ld.shared.b32 %0, [%1];" : "=r"(v) : "r"(a));
    return v;
}
__device__ __forceinline__ void mma16816(float* c, uint32_t a0, uint32_t a1,
                                         uint32_t a2, uint32_t a3,
                                         uint32_t b0, uint32_t b1) {
    asm volatile(
        "mma.sync.aligned.m16n8k16.row.col.f32.bf16.bf16.f32 "
        "{%0,%1,%2,%3}, {%4,%5,%6,%7}, {%8,%9}, {%0,%1,%2,%3};"
        : "+f"(c[0]), "+f"(c[1]), "+f"(c[2]), "+f"(c[3])
        : "r"(a0), "r"(a1), "r"(a2), "r"(a3), "r"(b0), "r"(b1));
}

typedef unsigned long long u64t;
__device__ __forceinline__ u64t pk2(float lo, float hi) {
    u64t r;
    asm("mov.b64 %0, {%1, %2};" : "=l"(r) : "f"(lo), "f"(hi));
    return r;
}
__device__ __forceinline__ void upk2(float& lo, float& hi, u64t v) {
    asm("mov.b64 {%0, %1}, %2;" : "=f"(lo), "=f"(hi) : "l"(v));
}
#define FMA2(d, a, b, c) \
    asm("fma.rn.f32x2 %0, %1, %2, %3;" : "=l"(d) : "l"(a), "l"(b), "l"(c))

// ================= weight prep: transpose + bf16 hi/lo split ===============
__global__ void prep_weights(const float* __restrict__ w0, const float* __restrict__ w1,
                             const float* __restrict__ w2)
{
    int m = blockIdx.x >> 9;          // 0..2
    int n = blockIdx.x & 511;         // 0..511
    int k = threadIdx.x;              // 0..255
    const float* W = (m == 0) ? w0 : (m == 1) ? w1 : w2;
    float x = W[(size_t)k * GHD + n];
    __nv_bfloat16 h = __float2bfloat16_rn(x);
    float r = x - __bfloat162float(h);
    __nv_bfloat16 l = __float2bfloat16_rn(r);
    size_t o = (size_t)m * GHD * GC + (size_t)n * GC + k;
    g_WhiT[o] = __bfloat16_as_ushort(h);
    g_WloT[o] = __bfloat16_as_ushort(l);
}

// ================= activation prep: bf16 hi/lo split =======================
__global__ void prep_act(const float* __restrict__ qin, const float* __restrict__ sin)
{
    const float* src = blockIdx.y ? sin : qin;
    unsigned short* dhi = g_Ahi + (size_t)blockIdx.y * GM * GC;
    unsigned short* dlo = g_Alo + (size_t)blockIdx.y * GM * GC;
    const size_t NF4 = (size_t)GM * GC / 4;   // 8388608
#pragma unroll
    for (int j = 0; j < 4; j++) {
        size_t i = (size_t)j * 2097152 + (size_t)blockIdx.x * 256 + threadIdx.x;
        if (i >= NF4) break;
        float4 x = ((const float4*)src)[i];
        float xs[4] = {x.x, x.y, x.z, x.w};
        unsigned short hs[4], ls[4];
#pragma unroll
        for (int e = 0; e < 4; e++) {
            __nv_bfloat16 h = __float2bfloat16_rn(xs[e]);
            __nv_bfloat16 l = __float2bfloat16_rn(xs[e] - __bfloat162float(h));
            hs[e] = __bfloat16_as_ushort(h);
            ls[e] = __bfloat16_as_ushort(l);
        }
        uint2 hp = {(uint32_t)hs[0] | ((uint32_t)hs[1] << 16),
                    (uint32_t)hs[2] | ((uint32_t)hs[3] << 16)};
        uint2 lp = {(uint32_t)ls[0] | ((uint32_t)ls[1] << 16),
                    (uint32_t)ls[2] | ((uint32_t)ls[3] << 16)};
        *(uint2*)&dhi[i * 4] = hp;
        *(uint2*)&dlo[i * 4] = lp;
    }
}

// ============== bf16x3 mma.sync GEMM: out[M,512]=A[M,256]@W^T+bias =========
// block tile 64(M) x 128(N), K chunks of 64 (4 k-steps), 2-stage cp.async,
// fragment-level pipelining to overlap LDS with MMA (kill the convoy).
// smem rows 144B stride (128B data + 16B pad): frag LDS conflict-free.
#define KC 64
#define RS 144
#define PLANE_A (64 * RS)           // 9216
#define PLANE_Bp (128 * RS)         // 18432
#define OFF_ALO PLANE_A
#define OFF_BHI (2 * PLANE_A)
#define OFF_BLO (2 * PLANE_A + PLANE_Bp)
#define STAGE_B (2 * PLANE_A + 2 * PLANE_Bp)    // 55296
#define GEMM_SMEM (2 * STAGE_B)                 // 110592

__global__ __launch_bounds__(256, 2)
void gemm_mma(const unsigned short* __restrict__ Ahi, const unsigned short* __restrict__ Alo,
              const unsigned short* __restrict__ Bhi, const unsigned short* __restrict__ Blo,
              const float* __restrict__ bias, float* __restrict__ out)
{
    extern __shared__ char smem[];
    const uint32_t sb = smem_to_u32(smem);
    const int tid = threadIdx.x;
    const int lane = tid & 31, wid = tid >> 5;
    const int warpM = wid & 1;        // 2 warps in M (32 rows each)
    const int warpN = wid >> 1;       // 4 warps in N (32 cols each)
    const int lr = lane >> 2, lc = lane & 3;
    const int ntile = blockIdx.x;     // 0..3
    const int mtile = blockIdx.y;     // 0..2047

    const char* pAhi = (const char*)Ahi + (size_t)mtile * 64 * 512;
    const char* pAlo = (const char*)Alo + (size_t)mtile * 64 * 512;
    const char* pBhi = (const char*)Bhi + (size_t)ntile * 128 * 512;
    const char* pBlo = (const char*)Blo + (size_t)ntile * 128 * 512;

    float acc[2][4][4];
#pragma unroll
    for (int i = 0; i < 2; i++)
#pragma unroll
        for (int j = 0; j < 4; j++)
#pragma unroll
            for (int e = 0; e < 4; e++) acc[i][j][e] = 0.f;

    // ---- async chunk loader: chunk c (64 k = 128B/row) into stage s -------
    auto load_chunk = [&](int c, int s) {
        uint32_t sbase = sb + s * STAGE_B;
        // A planes: 64 rows x 8 segs = 512 cp per plane (2/thread each)
#pragma unroll
        for (int t = 0; t < 2; t++) {
            int w = tid + t * 256;
            int row = w >> 3, s4 = w & 7;
            uint32_t so = sbase + row * RS + s4 * 16;
            size_t go = (size_t)row * 512 + c * 128 + s4 * 16;
            CP_ASYNC16(so, pAhi + go);
            CP_ASYNC16(so + OFF_ALO, pAlo + go);
        }
        // B planes: 128 rows x 8 segs = 1024 cp per plane (4/thread each)
#pragma unroll
        for (int t = 0; t < 4; t++) {
            int w = tid + t * 256;
            int row = w >> 3, s4 = w & 7;
            uint32_t so = sbase + OFF_BHI + row * RS + s4 * 16;
            size_t go = (size_t)row * 512 + c * 128 + s4 * 16;
            CP_ASYNC16(so, pBhi + go);
            CP_ASYNC16(so + PLANE_Bp, pBlo + go);
        }
        CP_COMMIT();
    };

    // fragment loaders (ks = 16-k step 0..3, offset ks*32 bytes)
    uint32_t aH[2][4], aL[2][4], bH[4][2], bL[4][2];
    auto ldA = [&](uint32_t (&rg)[2][4], uint32_t pb, int ks) {
        uint32_t a0 = pb + (warpM * 32 + lr) * RS + lc * 4 + ks * 32;
#pragma unroll
        for (int mt = 0; mt < 2; mt++) {
            uint32_t o = a0 + mt * 16 * RS;
            rg[mt][0] = lds32(o);
            rg[mt][1] = lds32(o + 8 * RS);
            rg[mt][2] = lds32(o + 16);
            rg[mt][3] = lds32(o + 8 * RS + 16);
        }
    };
    auto ldB = [&](uint32_t (&rg)[4][2], uint32_t pb, int ks) {
        uint32_t b0 = pb + (warpN * 32 + lr) * RS + lc * 4 + ks * 32;
#pragma unroll
        for (int nt = 0; nt < 4; nt++) {
            uint32_t o = b0 + nt * 8 * RS;
            rg[nt][0] = lds32(o);
            rg[nt][1] = lds32(o + 16);
        }
    };
    auto mma8 = [&](uint32_t (&A)[2][4], uint32_t (&B)[4][2]) {
#pragma unroll
        for (int mt = 0; mt < 2; mt++)
#pragma unroll
            for (int nt = 0; nt < 4; nt++)
                mma16816(acc[mt][nt], A[mt][0], A[mt][1], A[mt][2], A[mt][3],
                         B[nt][0], B[nt][1]);
    };

    const int NCH = GC / KC;    // 4
    load_chunk(0, 0);
    load_chunk(1, 1);
    CP_WAIT(1);
    __syncthreads();

    for (int c = 0; c < NCH; c++) {
        uint32_t stb = sb + (c & 1) * STAGE_B;
        // k-step pipeline: lo-frag loads overlap pass1/2 MMAs; next hi-frag
        // loads overlap pass3 MMAs.
        ldA(aH, stb, 0);
        ldB(bH, stb + OFF_BHI, 0);
#pragma unroll
        for (int ks = 0; ks < 4; ks++) {
            ldA(aL, stb + OFF_ALO, ks);
            ldB(bL, stb + OFF_BLO, ks);
            mma8(aH, bH);               // pass 1: hi*hi
            mma8(aH, bL);               // pass 2: hi*lo  (aH dead after)
            if (ks < 3) ldA(aH, stb, ks + 1);
            mma8(aL, bH);               // pass 3: lo*hi  (bH dead after)
            if (ks < 3) ldB(bH, stb + OFF_BHI, ks + 1);
        }
        if (c + 1 < NCH) {
            __syncthreads();
            if (c + 2 < NCH) { load_chunk(c + 2, c & 1); CP_WAIT(1); }
            else CP_WAIT(0);
            __syncthreads();
        }
    }

    // epilogue: bias + store
#pragma unroll
    for (int mt = 0; mt < 2; mt++) {
        int gm = mtile * 64 + warpM * 32 + mt * 16 + lr;
#pragma unroll
        for (int nt = 0; nt < 4; nt++) {
            int gn = ntile * 128 + warpN * 32 + nt * 8 + lc * 2;
            float2 bb = *(const float2*)&bias[gn];
            float2 o0, o1;
            o0.x = acc[mt][nt][0] + bb.x;
            o0.y = acc[mt][nt][1] + bb.y;
            o1.x = acc[mt][nt][2] + bb.x;
            o1.y = acc[mt][nt][3] + bb.y;
            *(float2*)&out[(size_t)gm * GHD + gn]       = o0;
            *(float2*)&out[(size_t)(gm + 8) * GHD + gn] = o1;
        }
    }
}

// ---------------- reduce stage 1: partial kv / ksum / vsum -----------------
#define RROWS 16

__global__ __launch_bounds__(256) void reduce_stage1(void)
{
    int chunk = blockIdx.x;
    int bh    = blockIdx.y;
    int b = bh >> 3, h = bh & 7;

    __shared__ float sk[RROWS][64];
    __shared__ float sv[RROWS][64];

    int tid  = threadIdx.x;
    int m    = tid & 63;
    int dg   = tid >> 6;
    int lane = tid & 31, warp = tid >> 5;
    int ldr = tid >> 4, ldc = (tid & 15) * 4;

    const float* kbase = g_k + (size_t)b * GN * GHD + h * GD;
    const float* vbase = g_v + (size_t)b * GN * GHD + h * GD;

    float acc[16];
#pragma unroll
    for (int j = 0; j < 16; j++) acc[j] = 0.f;
    float sacc = 0.f;

    int lend = (chunk + 1) * LCHUNK;
    for (int l0 = chunk * LCHUNK; l0 < lend; l0 += RROWS) {
        *(float4*)&sk[ldr][ldc] = *(const float4*)&kbase[(size_t)(l0 + ldr) * GHD + ldc];
        *(float4*)&sv[ldr][ldc] = *(const float4*)&vbase[(size_t)(l0 + ldr) * GHD + ldc];
        __syncthreads();
#pragma unroll
        for (int rr = 0; rr < 2; rr++) {
            int r = warp * 2 + rr;
            float x0 = sk[r][lane], x1 = sk[r][lane + 32];
            float ss = x0 * x0 + x1 * x1;
#pragma unroll
            for (int o = 16; o > 0; o >>= 1)
                ss += __shfl_xor_sync(0xffffffffu, ss, o);
            float inv = rsqrtf(ss);
            sk[r][lane]      = x0 * inv;
            sk[r][lane + 32] = x1 * inv;
        }
        __syncthreads();
#pragma unroll
        for (int r = 0; r < RROWS; r++) {
            float kval = sk[r][m];
            float4 v0 = *(const float4*)&sv[r][dg * 16 + 0];
            float4 v1 = *(const float4*)&sv[r][dg * 16 + 4];
            float4 v2 = *(const float4*)&sv[r][dg * 16 + 8];
            float4 v3 = *(const float4*)&sv[r][dg * 16 + 12];
            acc[0]  += kval * v0.x; acc[1]  += kval * v0.y;
            acc[2]  += kval * v0.z; acc[3]  += kval * v0.w;
            acc[4]  += kval * v1.x; acc[5]  += kval * v1.y;
            acc[6]  += kval * v1.z; acc[7]  += kval * v1.w;
            acc[8]  += kval * v2.x; acc[9]  += kval * v2.y;
            acc[10] += kval * v2.z; acc[11] += kval * v2.w;
            acc[12] += kval * v3.x; acc[13] += kval * v3.y;
            acc[14] += kval * v3.z; acc[15] += kval * v3.w;
            if (dg == 0)      sacc += kval;
            else if (dg == 1) sacc += sv[r][m];
        }
        __syncthreads();
    }

    float* dst = g_kvpart + ((size_t)chunk * 64 + bh) * 4224;
#pragma unroll
    for (int j = 0; j < 16; j++) dst[m * 64 + dg * 16 + j] = acc[j];
    if (dg == 0)      dst[4096 + m] = sacc;
    else if (dg == 1) dst[4160 + m] = sacc;
}

// ---------------- reduce stage 2 -------------------------------------------
__global__ void reduce_stage2(void)
{
    int i = blockIdx.x * blockDim.x + threadIdx.x;
    if (i >= 64 * 4224) return;
    float s = 0.f;
#pragma unroll 8
    for (int c = 0; c < CHUNKS; c++)
        s += g_kvpart[(size_t)c * 64 * 4224 + i];
    g_kvred[i] = s;
}

// ---------------- final ----------------------------------------------------
#define FROWS 64

__global__ __launch_bounds__(256) void final_kernel(float* __restrict__ out)
{
    __shared__ float sq[FROWS][GD];
    __shared__ float skv[GD][GD];
    __shared__ float sksum[GD];
    __shared__ float svsum[GD];
    __shared__ float sden[FROWS];

    int tid  = threadIdx.x;
    int dq   = tid & 15;
    int rg   = tid >> 4;
    int lane = tid & 31, warp = tid >> 5;

    size_t row0 = (size_t)blockIdx.x * FROWS;
    int b = (int)(row0 / GN);
    const float* qbase = g_q + row0 * GHD;
    const float Nf = (float)GN;

    float outacc[4][4];
#pragma unroll
    for (int i = 0; i < 4; i++)
#pragma unroll
        for (int j = 0; j < 4; j++) outacc[i][j] = 0.f;

    for (int h = 0; h < GH; h++) {
        const float* kvb = g_kvred + (size_t)(b * GH + h) * 4224;
#pragma unroll
        for (int t = 0; t < 4; t++)
            ((float4*)skv)[tid + t * 256] = ((const float4*)kvb)[tid + t * 256];
        if (tid < 64)        sksum[tid]      = kvb[4096 + tid];
        else if (tid < 128)  svsum[tid - 64] = kvb[4096 + tid];
#pragma unroll
        for (int t = 0; t < 16; t++) {
            int idx = tid + t * 256;
            int r = idx >> 6, c = idx & 63;
            sq[r][c] = qbase[(size_t)r * GHD + h * GD + c];
        }
        __syncthreads();

#pragma unroll
        for (int rr = 0; rr < 8; rr++) {
            int r = warp * 8 + rr;
            float x0 = sq[r][lane], x1 = sq[r][lane + 32];
            float ss = x0 * x0 + x1 * x1;
#pragma unroll
            for (int o = 16; o > 0; o >>= 1)
                ss += __shfl_xor_sync(0xffffffffu, ss, o);
            float inv = rsqrtf(ss);
            sq[r][lane]      = x0 * inv;
            sq[r][lane + 32] = x1 * inv;
        }
        __syncthreads();

#pragma unroll
        for (int rr = 0; rr < 8; rr++) {
            int r = warp * 8 + rr;
            float p = sq[r][lane] * sksum[lane] + sq[r][lane + 32] * sksum[lane + 32];
#pragma unroll
            for (int o = 16; o > 0; o >>= 1)
                p += __shfl_xor_sync(0xffffffffu, p, o);
            if (lane == 0) sden[r] = p + 2.f * Nf;
        }
        __syncthreads();

        // 4 rows x 4 d matvec, packed f32x2 math (2 FLOP / FFMA2)
        u64t a01[4], a23[4];
#pragma unroll
        for (int i = 0; i < 4; i++) { a01[i] = 0ull; a23[i] = 0ull; }

        for (int m = 0; m < GD; m++) {
            ulonglong2 kvp = *(const ulonglong2*)&skv[m][dq * 4];
#pragma unroll
            for (int i = 0; i < 4; i++) {
                float qv = sq[rg * 4 + i][m];
                u64t qq = pk2(qv, qv);
                FMA2(a01[i], qq, kvp.x, a01[i]);
                FMA2(a23[i], qq, kvp.y, a23[i]);
            }
        }
        float4 vsv = *(const float4*)&svsum[dq * 4];
#pragma unroll
        for (int i = 0; i < 4; i++) {
            float a0, a1, a2, a3;
            upk2(a0, a1, a01[i]);
            upk2(a2, a3, a23[i]);
            float rden = 1.f / sden[rg * 4 + i];
            outacc[i][0] += (a0 + Nf * vsv.x) * rden;
            outacc[i][1] += (a1 + Nf * vsv.y) * rden;
            outacc[i][2] += (a2 + Nf * vsv.z) * rden;
            outacc[i][3] += (a3 + Nf * vsv.w) * rden;
        }
        __syncthreads();
    }

#pragma unroll
    for (int i = 0; i < 4; i++) {
        float4 o;
        o.x = outacc[i][0] * (1.f / GH);
        o.y = outacc[i][1] * (1.f / GH);
        o.z = outacc[i][2] * (1.f / GH);
        o.w = outacc[i][3] * (1.f / GH);
        *(float4*)(out + (row0 + rg * 4 + i) * GD + dq * 4) = o;
    }
}

// ---------------- launch ---------------------------------------------------
extern "C" void kernel_launch(void* const* d_in, const int* in_sizes, int n_in,
                              void* d_out, int out_size)
{
    const float* q_in = (const float*)d_in[0];
    const float* s_in = (const float*)d_in[1];
    const float* Wq   = (const float*)d_in[2];
    const float* bq   = (const float*)d_in[3];
    const float* Wk   = (const float*)d_in[4];
    const float* bk   = (const float*)d_in[5];
    const float* Wv   = (const float*)d_in[6];
    const float* bv   = (const float*)d_in[7];
    float* out = (float*)d_out;

    float *gq, *gk, *gv;
    unsigned short *ahi, *alo, *whi, *wlo;
    cudaGetSymbolAddress((void**)&gq, g_q);
    cudaGetSymbolAddress((void**)&gk, g_k);
    cudaGetSymbolAddress((void**)&gv, g_v);
    cudaGetSymbolAddress((void**)&ahi, g_Ahi);
    cudaGetSymbolAddress((void**)&alo, g_Alo);
    cudaGetSymbolAddress((void**)&whi, g_WhiT);
    cudaGetSymbolAddress((void**)&wlo, g_WloT);

    static cudaStream_t s2 = nullptr;
    static cudaEvent_t evFork = nullptr, evJoin = nullptr;
    if (s2 == nullptr) {
        cudaFuncSetAttribute(gemm_mma, cudaFuncAttributeMaxDynamicSharedMemorySize, GEMM_SMEM);
        cudaStreamCreateWithFlags(&s2, cudaStreamNonBlocking);
        cudaEventCreateWithFlags(&evFork, cudaEventDisableTiming);
        cudaEventCreateWithFlags(&evJoin, cudaEventDisableTiming);
    }

    prep_weights<<<3 * GHD, 256>>>(Wq, Wk, Wv);
    prep_act<<<dim3(8192, 2), 256>>>(q_in, s_in);

    const size_t TA = (size_t)GM * GC;     // per-tensor activation plane size
    const size_t TW = (size_t)GHD * GC;    // per-matrix weight plane size
    dim3 ggrid(GHD / 128, GM / 64);        // (4, 2048)
    gemm_mma<<<ggrid, 256, GEMM_SMEM>>>(ahi + TA, alo + TA, whi + TW,     wlo + TW,     bk, gk);
    gemm_mma<<<ggrid, 256, GEMM_SMEM>>>(ahi + TA, alo + TA, whi + 2 * TW, wlo + 2 * TW, bv, gv);

    // fork: q-projection (tensor-bound) overlaps the kv reduction (mem-bound)
    cudaEventRecord(evFork, 0);
    cudaStreamWaitEvent(s2, evFork, 0);
    gemm_mma<<<ggrid, 256, GEMM_SMEM, s2>>>(ahi, alo, whi, wlo, bq, gq);

    reduce_stage1<<<dim3(CHUNKS, 64), 256>>>();
    reduce_stage2<<<(64 * 4224 + 255) / 256, 256>>>();

    cudaEventRecord(evJoin, s2);
    cudaStreamWaitEvent(0, evJoin, 0);

    final_kernel<<<GM / FROWS, 256>>>(out);
}

// round 12
// speedup vs baseline: 1.8110x; 1.0226x over previous
#include <cuda_runtime.h>
#include <cuda_bf16.h>
#include <cstdint>

// Problem constants
#define GB 8
#define GN 16384
#define GC 256
#define GH 8
#define GD 64
#define GHD 512
#define GM (GB*GN)          // 131072 flattened rows

// ---------------- scratch (device globals; no allocation allowed) ----------
__device__ float g_q[(size_t)GM * GHD];
__device__ float g_k[(size_t)GM * GHD];
__device__ float g_v[(size_t)GM * GHD];

// activation bf16 hi/lo planes: [2 tensors][M][256]
__device__ unsigned short g_Ahi[(size_t)2 * GM * GC];
__device__ unsigned short g_Alo[(size_t)2 * GM * GC];

// transposed + bf16-split weights: [3][N=512][K=256]
__device__ unsigned short g_WhiT[3 * GHD * GC];
__device__ unsigned short g_WloT[3 * GHD * GC];

#define CHUNKS 64
#define LCHUNK (GN / CHUNKS)              // 256
// per (chunk, b*h): 4096 kv + 64 ksum + 64 vsum = 4224 floats
__device__ float g_kvpart[(size_t)CHUNKS * 64 * 4224];
__device__ float g_kvred[(size_t)64 * 4224];

// ======================= helpers ===========================================
__device__ __forceinline__ uint32_t smem_to_u32(const void* p) {
    uint32_t a;
    asm("{ .reg .u64 t; cvta.to.shared.u64 t, %1; cvt.u32.u64 %0, t; }" : "=r"(a) : "l"(p));
    return a;
}
#define CP_ASYNC16(dst, src) \
    asm volatile("cp.async.cg.shared.global [%0], [%1], 16;" :: "r"(dst), "l"(src))
#define CP_COMMIT() asm volatile("cp.async.commit_group;" ::: "memory")
#define CP_WAIT(n)  asm volatile("cp.async.wait_group %0;" :: "n"(n) : "memory")

#define LDSM4(r0, r1, r2, r3, addr) \
    asm volatile("ldmatrix.sync.aligned.m8n8.x4.shared.b16 {%0,%1,%2,%3}, [%4];" \
        : "=r"(r0), "=r"(r1), "=r"(r2), "=r"(r3) : "r"(addr))

__device__ __forceinline__ void mma16816(float* c, uint32_t a0, uint32_t a1,
                                         uint32_t a2, uint32_t a3,
                                         uint32_t b0, uint32_t b1) {
    asm volatile(
        "mma.sync.aligned.m16n8k16.row.col.f32.bf16.bf16.f32 "
        "{%0,%1,%2,%3}, {%4,%5,%6,%7}, {%8,%9}, {%0,%1,%2,%3};"
        : "+f"(c[0]), "+f"(c[1]), "+f"(c[2]), "+f"(c[3])
        : "r"(a0), "r"(a1), "r"(a2), "r"(a3), "r"(b0), "r"(b1));
}

typedef unsigned long long u64t;
__device__ __forceinline__ u64t pk2(float lo, float hi) {
    u64t r;
    asm("mov.b64 %0, {%1, %2};" : "=l"(r) : "f"(lo), "f"(hi));
    return r;
}
__device__ __forceinline__ void upk2(float& lo, float& hi, u64t v) {
    asm("mov.b64 {%0, %1}, %2;" : "=f"(lo), "=f"(hi) : "l"(v));
}
#define FMA2(d, a, b, c) \
    asm("fma.rn.f32x2 %0, %1, %2, %3;" : "=l"(d) : "l"(a), "l"(b), "l"(c))

// ================= weight prep: transpose + bf16 hi/lo split ===============
__global__ void prep_weights(const float* __restrict__ w0, const float* __restrict__ w1,
                             const float* __restrict__ w2)
{
    int m = blockIdx.x >> 9;          // 0..2
    int n = blockIdx.x & 511;         // 0..511
    int k = threadIdx.x;              // 0..255
    const float* W = (m == 0) ? w0 : (m == 1) ? w1 : w2;
    float x = W[(size_t)k * GHD + n];
    __nv_bfloat16 h = __float2bfloat16_rn(x);
    float r = x - __bfloat162float(h);
    __nv_bfloat16 l = __float2bfloat16_rn(r);
    size_t o = (size_t)m * GHD * GC + (size_t)n * GC + k;
    g_WhiT[o] = __bfloat16_as_ushort(h);
    g_WloT[o] = __bfloat16_as_ushort(l);
}

// ================= activation prep: bf16 hi/lo split =======================
__global__ void prep_act(const float* __restrict__ qin, const float* __restrict__ sin)
{
    const float* src = blockIdx.y ? sin : qin;
    unsigned short* dhi = g_Ahi + (size_t)blockIdx.y * GM * GC;
    unsigned short* dlo = g_Alo + (size_t)blockIdx.y * GM * GC;
    const size_t NF4 = (size_t)GM * GC / 4;   // 8388608
#pragma unroll
    for (int j = 0; j < 4; j++) {
        size_t i = (size_t)j * 2097152 + (size_t)blockIdx.x * 256 + threadIdx.x;
        if (i >= NF4) break;
        float4 x = ((const float4*)src)[i];
        float xs[4] = {x.x, x.y, x.z, x.w};
        unsigned short hs[4], ls[4];
#pragma unroll
        for (int e = 0; e < 4; e++) {
            __nv_bfloat16 h = __float2bfloat16_rn(xs[e]);
            __nv_bfloat16 l = __float2bfloat16_rn(xs[e] - __bfloat162float(h));
            hs[e] = __bfloat16_as_ushort(h);
            ls[e] = __bfloat16_as_ushort(l);
        }
        uint2 hp = {(uint32_t)hs[0] | ((uint32_t)hs[1] << 16),
                    (uint32_t)hs[2] | ((uint32_t)hs[3] << 16)};
        uint2 lp = {(uint32_t)ls[0] | ((uint32_t)ls[1] << 16),
                    (uint32_t)ls[2] | ((uint32_t)ls[3] << 16)};
        *(uint2*)&dhi[i * 4] = hp;
        *(uint2*)&dlo[i * 4] = lp;
    }
}

// ============== bf16x3 mma.sync GEMM: out[M,512]=A[M,256]@W^T+bias =========
// block tile 64(M) x 128(N), K chunks of 64 (4 k-steps), 2-stage cp.async,
// ldmatrix.x4 fragment loads (4x fewer shared-pipe instructions than lds32).
// smem rows 144B stride: LDSM tiles provably bank-conflict-free.
#define KC 64
#define RS 144
#define PLANE_A (64 * RS)           // 9216
#define PLANE_Bp (128 * RS)         // 18432
#define OFF_ALO PLANE_A
#define OFF_BHI (2 * PLANE_A)
#define OFF_BLO (2 * PLANE_A + PLANE_Bp)
#define STAGE_B (2 * PLANE_A + 2 * PLANE_Bp)    // 55296
#define GEMM_SMEM (2 * STAGE_B)                 // 110592

__global__ __launch_bounds__(256, 2)
void gemm_mma(const unsigned short* __restrict__ Ahi, const unsigned short* __restrict__ Alo,
              const unsigned short* __restrict__ Bhi, const unsigned short* __restrict__ Blo,
              const float* __restrict__ bias, float* __restrict__ out)
{
    extern __shared__ char smem[];
    const uint32_t sb = smem_to_u32(smem);
    const int tid = threadIdx.x;
    const int lane = tid & 31, wid = tid >> 5;
    const int warpM = wid & 1;        // 2 warps in M (32 rows each)
    const int warpN = wid >> 1;       // 4 warps in N (32 cols each)
    const int lr = lane >> 2, lc = lane & 3;
    const int ntile = blockIdx.x;     // 0..3
    const int mtile = blockIdx.y;     // 0..2047

    const char* pAhi = (const char*)Ahi + (size_t)mtile * 64 * 512;
    const char* pAlo = (const char*)Alo + (size_t)mtile * 64 * 512;
    const char* pBhi = (const char*)Bhi + (size_t)ntile * 128 * 512;
    const char* pBlo = (const char*)Blo + (size_t)ntile * 128 * 512;

    float acc[2][4][4];
#pragma unroll
    for (int i = 0; i < 2; i++)
#pragma unroll
        for (int j = 0; j < 4; j++)
#pragma unroll
            for (int e = 0; e < 4; e++) acc[i][j][e] = 0.f;

    // ldmatrix lane bases (byte offsets within a plane)
    // A x4 tiles -> {a0,a1,a2,a3} = {(m0-7,kLo),(m8-15,kLo),(m0-7,kHi),(m8-15,kHi)}
    const uint32_t aRowBase =
        (uint32_t)(warpM * 32 + (lane & 7) + ((lane & 8) ? 8 : 0)) * RS
        + ((lane & 16) ? 16 : 0);
    // B x4 tiles (ntp covers nt=2*ntp,2*ntp+1):
    // {b[nt][0], b[nt][1], b[nt+1][0], b[nt+1][1]}
    const uint32_t bRowBase =
        (uint32_t)(warpN * 32 + (lane & 7) + ((lane & 16) ? 8 : 0)) * RS
        + ((lane & 8) ? 16 : 0);

    // ---- async chunk loader: chunk c (64 k = 128B/row) into stage s -------
    auto load_chunk = [&](int c, int s) {
        uint32_t sbase = sb + s * STAGE_B;
#pragma unroll
        for (int t = 0; t < 2; t++) {
            int w = tid + t * 256;
            int row = w >> 3, s4 = w & 7;
            uint32_t so = sbase + row * RS + s4 * 16;
            size_t go = (size_t)row * 512 + c * 128 + s4 * 16;
            CP_ASYNC16(so, pAhi + go);
            CP_ASYNC16(so + OFF_ALO, pAlo + go);
        }
#pragma unroll
        for (int t = 0; t < 4; t++) {
            int w = tid + t * 256;
            int row = w >> 3, s4 = w & 7;
            uint32_t so = sbase + OFF_BHI + row * RS + s4 * 16;
            size_t go = (size_t)row * 512 + c * 128 + s4 * 16;
            CP_ASYNC16(so, pBhi + go);
            CP_ASYNC16(so + PLANE_Bp, pBlo + go);
        }
        CP_COMMIT();
    };

    uint32_t aH[2][4], aL[2][4], bH[4][2], bL[4][2];
    auto ldA = [&](uint32_t (&rg)[2][4], uint32_t planeBase, int ks) {
        uint32_t a0 = planeBase + aRowBase + ks * 32;
#pragma unroll
        for (int mt = 0; mt < 2; mt++)
            LDSM4(rg[mt][0], rg[mt][1], rg[mt][2], rg[mt][3], a0 + mt * 16 * RS);
    };
    auto ldB = [&](uint32_t (&rg)[4][2], uint32_t planeBase, int ks) {
        uint32_t b0 = planeBase + bRowBase + ks * 32;
#pragma unroll
        for (int ntp = 0; ntp < 2; ntp++)
            LDSM4(rg[ntp * 2][0], rg[ntp * 2][1], rg[ntp * 2 + 1][0], rg[ntp * 2 + 1][1],
                  b0 + ntp * 16 * RS);
    };
    auto mma8 = [&](uint32_t (&A)[2][4], uint32_t (&B)[4][2]) {
#pragma unroll
        for (int mt = 0; mt < 2; mt++)
#pragma unroll
            for (int nt = 0; nt < 4; nt++)
                mma16816(acc[mt][nt], A[mt][0], A[mt][1], A[mt][2], A[mt][3],
                         B[nt][0], B[nt][1]);
    };

    const int NCH = GC / KC;    // 4
    load_chunk(0, 0);
    load_chunk(1, 1);
    CP_WAIT(1);
    __syncthreads();

    for (int c = 0; c < NCH; c++) {
        uint32_t stb = sb + (c & 1) * STAGE_B;
        ldA(aH, stb, 0);
        ldB(bH, stb + OFF_BHI, 0);
#pragma unroll
        for (int ks = 0; ks < 4; ks++) {
            ldA(aL, stb + OFF_ALO, ks);
            ldB(bL, stb + OFF_BLO, ks);
            mma8(aH, bH);               // pass 1: hi*hi
            mma8(aH, bL);               // pass 2: hi*lo  (aH dead after)
            if (ks < 3) ldA(aH, stb, ks + 1);
            mma8(aL, bH);               // pass 3: lo*hi  (bH dead after)
            if (ks < 3) ldB(bH, stb + OFF_BHI, ks + 1);
        }
        if (c + 1 < NCH) {
            __syncthreads();
            if (c + 2 < NCH) { load_chunk(c + 2, c & 1); CP_WAIT(1); }
            else CP_WAIT(0);
            __syncthreads();
        }
    }

    // epilogue: bias + store
#pragma unroll
    for (int mt = 0; mt < 2; mt++) {
        int gm = mtile * 64 + warpM * 32 + mt * 16 + lr;
#pragma unroll
        for (int nt = 0; nt < 4; nt++) {
            int gn = ntile * 128 + warpN * 32 + nt * 8 + lc * 2;
            float2 bb = *(const float2*)&bias[gn];
            float2 o0, o1;
            o0.x = acc[mt][nt][0] + bb.x;
            o0.y = acc[mt][nt][1] + bb.y;
            o1.x = acc[mt][nt][2] + bb.x;
            o1.y = acc[mt][nt][3] + bb.y;
            *(float2*)&out[(size_t)gm * GHD + gn]       = o0;
            *(float2*)&out[(size_t)(gm + 8) * GHD + gn] = o1;
        }
    }
}

// ---------------- reduce stage 1: partial kv / ksum / vsum -----------------
#define RROWS 16

__global__ __launch_bounds__(256) void reduce_stage1(void)
{
    int chunk = blockIdx.x;
    int bh    = blockIdx.y;
    int b = bh >> 3, h = bh & 7;

    __shared__ float sk[RROWS][64];
    __shared__ float sv[RROWS][64];

    int tid  = threadIdx.x;
    int m    = tid & 63;
    int dg   = tid >> 6;
    int lane = tid & 31, warp = tid >> 5;
    int ldr = tid >> 4, ldc = (tid & 15) * 4;

    const float* kbase = g_k + (size_t)b * GN * GHD + h * GD;
    const float* vbase = g_v + (size_t)b * GN * GHD + h * GD;

    float acc[16];
#pragma unroll
    for (int j = 0; j < 16; j++) acc[j] = 0.f;
    float sacc = 0.f;

    int lend = (chunk + 1) * LCHUNK;
    for (int l0 = chunk * LCHUNK; l0 < lend; l0 += RROWS) {
        *(float4*)&sk[ldr][ldc] = *(const float4*)&kbase[(size_t)(l0 + ldr) * GHD + ldc];
        *(float4*)&sv[ldr][ldc] = *(const float4*)&vbase[(size_t)(l0 + ldr) * GHD + ldc];
        __syncthreads();
#pragma unroll
        for (int rr = 0; rr < 2; rr++) {
            int r = warp * 2 + rr;
            float x0 = sk[r][lane], x1 = sk[r][lane + 32];
            float ss = x0 * x0 + x1 * x1;
#pragma unroll
            for (int o = 16; o > 0; o >>= 1)
                ss += __shfl_xor_sync(0xffffffffu, ss, o);
            float inv = rsqrtf(ss);
            sk[r][lane]      = x0 * inv;
            sk[r][lane + 32] = x1 * inv;
        }
        __syncthreads();
#pragma unroll
        for (int r = 0; r < RROWS; r++) {
            float kval = sk[r][m];
            float4 v0 = *(const float4*)&sv[r][dg * 16 + 0];
            float4 v1 = *(const float4*)&sv[r][dg * 16 + 4];
            float4 v2 = *(const float4*)&sv[r][dg * 16 + 8];
            float4 v3 = *(const float4*)&sv[r][dg * 16 + 12];
            acc[0]  += kval * v0.x; acc[1]  += kval * v0.y;
            acc[2]  += kval * v0.z; acc[3]  += kval * v0.w;
            acc[4]  += kval * v1.x; acc[5]  += kval * v1.y;
            acc[6]  += kval * v1.z; acc[7]  += kval * v1.w;
            acc[8]  += kval * v2.x; acc[9]  += kval * v2.y;
            acc[10] += kval * v2.z; acc[11] += kval * v2.w;
            acc[12] += kval * v3.x; acc[13] += kval * v3.y;
            acc[14] += kval * v3.z; acc[15] += kval * v3.w;
            if (dg == 0)      sacc += kval;
            else if (dg == 1) sacc += sv[r][m];
        }
        __syncthreads();
    }

    float* dst = g_kvpart + ((size_t)chunk * 64 + bh) * 4224;
#pragma unroll
    for (int j = 0; j < 16; j++) dst[m * 64 + dg * 16 + j] = acc[j];
    if (dg == 0)      dst[4096 + m] = sacc;
    else if (dg == 1) dst[4160 + m] = sacc;
}

// ---------------- reduce stage 2 -------------------------------------------
__global__ void reduce_stage2(void)
{
    int i = blockIdx.x * blockDim.x + threadIdx.x;
    if (i >= 64 * 4224) return;
    float s = 0.f;
#pragma unroll 8
    for (int c = 0; c < CHUNKS; c++)
        s += g_kvpart[(size_t)c * 64 * 4224 + i];
    g_kvred[i] = s;
}

// ---------------- final ----------------------------------------------------
#define FROWS 64

__global__ __launch_bounds__(256) void final_kernel(float* __restrict__ out)
{
    __shared__ float sq[FROWS][GD];
    __shared__ float skv[GD][GD];
    __shared__ float sksum[GD];
    __shared__ float svsum[GD];
    __shared__ float sden[FROWS];

    int tid  = threadIdx.x;
    int dq   = tid & 15;
    int rg   = tid >> 4;
    int lane = tid & 31, warp = tid >> 5;

    size_t row0 = (size_t)blockIdx.x * FROWS;
    int b = (int)(row0 / GN);
    const float* qbase = g_q + row0 * GHD;
    const float Nf = (float)GN;

    float outacc[4][4];
#pragma unroll
    for (int i = 0; i < 4; i++)
#pragma unroll
        for (int j = 0; j < 4; j++) outacc[i][j] = 0.f;

    for (int h = 0; h < GH; h++) {
        const float* kvb = g_kvred + (size_t)(b * GH + h) * 4224;
#pragma unroll
        for (int t = 0; t < 4; t++)
            ((float4*)skv)[tid + t * 256] = ((const float4*)kvb)[tid + t * 256];
        if (tid < 64)        sksum[tid]      = kvb[4096 + tid];
        else if (tid < 128)  svsum[tid - 64] = kvb[4096 + tid];
#pragma unroll
        for (int t = 0; t < 16; t++) {
            int idx = tid + t * 256;
            int r = idx >> 6, c = idx & 63;
            sq[r][c] = qbase[(size_t)r * GHD + h * GD + c];
        }
        __syncthreads();

#pragma unroll
        for (int rr = 0; rr < 8; rr++) {
            int r = warp * 8 + rr;
            float x0 = sq[r][lane], x1 = sq[r][lane + 32];
            float ss = x0 * x0 + x1 * x1;
#pragma unroll
            for (int o = 16; o > 0; o >>= 1)
                ss += __shfl_xor_sync(0xffffffffu, ss, o);
            float inv = rsqrtf(ss);
            sq[r][lane]      = x0 * inv;
            sq[r][lane + 32] = x1 * inv;
        }
        __syncthreads();

#pragma unroll
        for (int rr = 0; rr < 8; rr++) {
            int r = warp * 8 + rr;
            float p = sq[r][lane] * sksum[lane] + sq[r][lane + 32] * sksum[lane + 32];
#pragma unroll
            for (int o = 16; o > 0; o >>= 1)
                p += __shfl_xor_sync(0xffffffffu, p, o);
            if (lane == 0) sden[r] = p + 2.f * Nf;
        }
        __syncthreads();

        // 4 rows x 4 d matvec, packed f32x2 math (2 FLOP / FFMA2)
        u64t a01[4], a23[4];
#pragma unroll
        for (int i = 0; i < 4; i++) { a01[i] = 0ull; a23[i] = 0ull; }

        for (int m = 0; m < GD; m++) {
            ulonglong2 kvp = *(const ulonglong2*)&skv[m][dq * 4];
#pragma unroll
            for (int i = 0; i < 4; i++) {
                float qv = sq[rg * 4 + i][m];
                u64t qq = pk2(qv, qv);
                FMA2(a01[i], qq, kvp.x, a01[i]);
                FMA2(a23[i], qq, kvp.y, a23[i]);
            }
        }
        float4 vsv = *(const float4*)&svsum[dq * 4];
#pragma unroll
        for (int i = 0; i < 4; i++) {
            float a0, a1, a2, a3;
            upk2(a0, a1, a01[i]);
            upk2(a2, a3, a23[i]);
            float rden = 1.f / sden[rg * 4 + i];
            outacc[i][0] += (a0 + Nf * vsv.x) * rden;
            outacc[i][1] += (a1 + Nf * vsv.y) * rden;
            outacc[i][2] += (a2 + Nf * vsv.z) * rden;
            outacc[i][3] += (a3 + Nf * vsv.w) * rden;
        }
        __syncthreads();
    }

#pragma unroll
    for (int i = 0; i < 4; i++) {
        float4 o;
        o.x = outacc[i][0] * (1.f / GH);
        o.y = outacc[i][1] * (1.f / GH);
        o.z = outacc[i][2] * (1.f / GH);
        o.w = outacc[i][3] * (1.f / GH);
        *(float4*)(out + (row0 + rg * 4 + i) * GD + dq * 4) = o;
    }
}

// ---------------- launch ---------------------------------------------------
extern "C" void kernel_launch(void* const* d_in, const int* in_sizes, int n_in,
                              void* d_out, int out_size)
{
    const float* q_in = (const float*)d_in[0];
    const float* s_in = (const float*)d_in[1];
    const float* Wq   = (const float*)d_in[2];
    const float* bq   = (const float*)d_in[3];
    const float* Wk   = (const float*)d_in[4];
    const float* bk   = (const float*)d_in[5];
    const float* Wv   = (const float*)d_in[6];
    const float* bv   = (const float*)d_in[7];
    float* out = (float*)d_out;

    float *gq, *gk, *gv;
    unsigned short *ahi, *alo, *whi, *wlo;
    cudaGetSymbolAddress((void**)&gq, g_q);
    cudaGetSymbolAddress((void**)&gk, g_k);
    cudaGetSymbolAddress((void**)&gv, g_v);
    cudaGetSymbolAddress((void**)&ahi, g_Ahi);
    cudaGetSymbolAddress((void**)&alo, g_Alo);
    cudaGetSymbolAddress((void**)&whi, g_WhiT);
    cudaGetSymbolAddress((void**)&wlo, g_WloT);

    static cudaStream_t s2 = nullptr;
    static cudaEvent_t evFork = nullptr, evJoin = nullptr;
    if (s2 == nullptr) {
        cudaFuncSetAttribute(gemm_mma, cudaFuncAttributeMaxDynamicSharedMemorySize, GEMM_SMEM);
        cudaStreamCreateWithFlags(&s2, cudaStreamNonBlocking);
        cudaEventCreateWithFlags(&evFork, cudaEventDisableTiming);
        cudaEventCreateWithFlags(&evJoin, cudaEventDisableTiming);
    }

    prep_weights<<<3 * GHD, 256>>>(Wq, Wk, Wv);
    prep_act<<<dim3(8192, 2), 256>>>(q_in, s_in);

    const size_t TA = (size_t)GM * GC;     // per-tensor activation plane size
    const size_t TW = (size_t)GHD * GC;    // per-matrix weight plane size
    dim3 ggrid(GHD / 128, GM / 64);        // (4, 2048)
    gemm_mma<<<ggrid, 256, GEMM_SMEM>>>(ahi + TA, alo + TA, whi + TW,     wlo + TW,     bk, gk);
    gemm_mma<<<ggrid, 256, GEMM_SMEM>>>(ahi + TA, alo + TA, whi + 2 * TW, wlo + 2 * TW, bv, gv);

    // fork: q-projection (tensor-bound) overlaps the kv reduction (mem-bound)
    cudaEventRecord(evFork, 0);
    cudaStreamWaitEvent(s2, evFork, 0);
    gemm_mma<<<ggrid, 256, GEMM_SMEM, s2>>>(ahi, alo, whi, wlo, bq, gq);

    reduce_stage1<<<dim3(CHUNKS, 64), 256>>>();
    reduce_stage2<<<(64 * 4224 + 255) / 256, 256>>>();

    cudaEventRecord(evJoin, s2);
    cudaStreamWaitEvent(0, evJoin, 0);

    final_kernel<<<GM / FROWS, 256>>>(out);
}

// round 15
// speedup vs baseline: 2.5217x; 1.3924x over previous
#include <cuda_runtime.h>
#include <cuda_fp16.h>
#include <cstdint>

// Problem constants
#define GB 8
#define GN 16384
#define GC 256
#define GH 8
#define GD 64
#define GHD 512
#define GM (GB*GN)          // 131072 flattened rows

// ---------------- scratch (device globals; no allocation allowed) ----------
__device__ float g_q[(size_t)GM * GHD];
__device__ float g_k[(size_t)GM * GHD];
__device__ float g_v[(size_t)GM * GHD];

// activation fp16 plane: [2 tensors][M][256]
__device__ unsigned short g_Ah[(size_t)2 * GM * GC];
// transposed fp16 weights: [3][N=512][K=256]
__device__ unsigned short g_WhT[3 * GHD * GC];

#define CHUNKS 64
#define LCHUNK (GN / CHUNKS)              // 256
// per (chunk, b*h): 4096 kv + 64 ksum + 64 vsum = 4224 floats
__device__ float g_kvpart[(size_t)CHUNKS * 64 * 4224];
__device__ float g_kvred[(size_t)64 * 4224];

// ======================= helpers ===========================================
__device__ __forceinline__ uint32_t smem_to_u32(const void* p) {
    uint32_t a;
    asm("{ .reg .u64 t; cvta.to.shared.u64 t, %1; cvt.u32.u64 %0, t; }" : "=r"(a) : "l"(p));
    return a;
}
#define CP_ASYNC16(dst, src) \
    asm volatile("cp.async.cg.shared.global [%0], [%1], 16;" :: "r"(dst), "l"(src))
#define CP_COMMIT() asm volatile("cp.async.commit_group;" ::: "memory")
#define CP_WAIT(n)  asm volatile("cp.async.wait_group %0;" :: "n"(n) : "memory")

#define LDSM4(r0, r1, r2, r3, addr) \
    asm volatile("ldmatrix.sync.aligned.m8n8.x4.shared.b16 {%0,%1,%2,%3}, [%4];" \
        : "=r"(r0), "=r"(r1), "=r"(r2), "=r"(r3) : "r"(addr))

__device__ __forceinline__ void mma16816h(float* c, uint32_t a0, uint32_t a1,
                                          uint32_t a2, uint32_t a3,
                                          uint32_t b0, uint32_t b1) {
    asm volatile(
        "mma.sync.aligned.m16n8k16.row.col.f32.f16.f16.f32 "
        "{%0,%1,%2,%3}, {%4,%5,%6,%7}, {%8,%9}, {%0,%1,%2,%3};"
        : "+f"(c[0]), "+f"(c[1]), "+f"(c[2]), "+f"(c[3])
        : "r"(a0), "r"(a1), "r"(a2), "r"(a3), "r"(b0), "r"(b1));
}

typedef unsigned long long u64t;
__device__ __forceinline__ u64t pk2(float lo, float hi) {
    u64t r;
    asm("mov.b64 %0, {%1, %2};" : "=l"(r) : "f"(lo), "f"(hi));
    return r;
}
__device__ __forceinline__ void upk2(float& lo, float& hi, u64t v) {
    asm("mov.b64 {%0, %1}, %2;" : "=f"(lo), "=f"(hi) : "l"(v));
}
#define FMA2(d, a, b, c) \
    asm("fma.rn.f32x2 %0, %1, %2, %3;" : "=l"(d) : "l"(a), "l"(b), "l"(c))

// ================= weight prep: transpose + fp16 ===========================
__global__ void prep_weights(const float* __restrict__ w0, const float* __restrict__ w1,
                             const float* __restrict__ w2)
{
    int m = blockIdx.x >> 9;          // 0..2
    int n = blockIdx.x & 511;         // 0..511
    int k = threadIdx.x;              // 0..255
    const float* W = (m == 0) ? w0 : (m == 1) ? w1 : w2;
    float x = W[(size_t)k * GHD + n];
    g_WhT[(size_t)m * GHD * GC + (size_t)n * GC + k] =
        __half_as_ushort(__float2half_rn(x));
}

// ================= activation prep: fp16 ===================================
__global__ void prep_act(const float* __restrict__ qin, const float* __restrict__ sin)
{
    const float* src = blockIdx.y ? sin : qin;
    unsigned short* dst = g_Ah + (size_t)blockIdx.y * GM * GC;
    const size_t NF4 = (size_t)GM * GC / 4;   // 8388608
#pragma unroll
    for (int j = 0; j < 4; j++) {
        size_t i = (size_t)j * 2097152 + (size_t)blockIdx.x * 256 + threadIdx.x;
        if (i >= NF4) break;
        float4 x = ((const float4*)src)[i];
        unsigned short hs[4];
        hs[0] = __half_as_ushort(__float2half_rn(x.x));
        hs[1] = __half_as_ushort(__float2half_rn(x.y));
        hs[2] = __half_as_ushort(__float2half_rn(x.z));
        hs[3] = __half_as_ushort(__float2half_rn(x.w));
        uint2 hp = {(uint32_t)hs[0] | ((uint32_t)hs[1] << 16),
                    (uint32_t)hs[2] | ((uint32_t)hs[3] << 16)};
        *(uint2*)&dst[i * 4] = hp;
    }
}

// ============ fp16 single-pass mma GEMM: out[M,512]=A@W^T+bias =============
// block tile 64(M) x 128(N), K chunks of 64 (4 k-steps), 2-stage cp.async,
// ldmatrix.x4 frag loads, fragment double-buffering across k-steps.
// smem rows 144B stride: LDSM tiles bank-conflict-free.
#define KC 64
#define RS 144
#define PLANE_A (64 * RS)           // 9216
#define PLANE_Bp (128 * RS)         // 18432
#define OFF_B PLANE_A
#define STAGE_B (PLANE_A + PLANE_Bp)    // 27648
#define GEMM_SMEM (2 * STAGE_B)         // 55296

__global__ __launch_bounds__(256, 2)
void gemm_mma(const unsigned short* __restrict__ Ah,
              const unsigned short* __restrict__ Bh,
              const float* __restrict__ bias, float* __restrict__ out)
{
    extern __shared__ char smem[];
    const uint32_t sb = smem_to_u32(smem);
    const int tid = threadIdx.x;
    const int lane = tid & 31, wid = tid >> 5;
    const int warpM = wid & 1;        // 2 warps in M (32 rows each)
    const int warpN = wid >> 1;       // 4 warps in N (32 cols each)
    const int lr = lane >> 2, lc = lane & 3;
    const int ntile = blockIdx.x;     // 0..3
    const int mtile = blockIdx.y;     // 0..2047

    const char* pA = (const char*)Ah + (size_t)mtile * 64 * 512;
    const char* pB = (const char*)Bh + (size_t)ntile * 128 * 512;

    float acc[2][4][4];
#pragma unroll
    for (int i = 0; i < 2; i++)
#pragma unroll
        for (int j = 0; j < 4; j++)
#pragma unroll
            for (int e = 0; e < 4; e++) acc[i][j][e] = 0.f;

    // ldmatrix lane bases (byte offsets within a plane)
    const uint32_t aRowBase =
        (uint32_t)(warpM * 32 + (lane & 7) + ((lane & 8) ? 8 : 0)) * RS
        + ((lane & 16) ? 16 : 0);
    const uint32_t bRowBase =
        (uint32_t)(warpN * 32 + (lane & 7) + ((lane & 16) ? 8 : 0)) * RS
        + ((lane & 8) ? 16 : 0);

    // ---- async chunk loader: chunk c (64 k = 128B/row) into stage s -------
    auto load_chunk = [&](int c, int s) {
        uint32_t sbase = sb + s * STAGE_B;
#pragma unroll
        for (int t = 0; t < 2; t++) {
            int w = tid + t * 256;
            int row = w >> 3, s4 = w & 7;
            CP_ASYNC16(sbase + row * RS + s4 * 16,
                       pA + (size_t)row * 512 + c * 128 + s4 * 16);
        }
#pragma unroll
        for (int t = 0; t < 4; t++) {
            int w = tid + t * 256;
            int row = w >> 3, s4 = w & 7;
            CP_ASYNC16(sbase + OFF_B + row * RS + s4 * 16,
                       pB + (size_t)row * 512 + c * 128 + s4 * 16);
        }
        CP_COMMIT();
    };

    uint32_t aF[2][2][4], bF[2][4][2];   // [parity][...]
    auto ldA = [&](uint32_t (&rg)[2][4], uint32_t stb, int ks) {
        uint32_t a0 = stb + aRowBase + ks * 32;
#pragma unroll
        for (int mt = 0; mt < 2; mt++)
            LDSM4(rg[mt][0], rg[mt][1], rg[mt][2], rg[mt][3], a0 + mt * 16 * RS);
    };
    auto ldB = [&](uint32_t (&rg)[4][2], uint32_t stb, int ks) {
        uint32_t b0 = stb + OFF_B + bRowBase + ks * 32;
#pragma unroll
        for (int ntp = 0; ntp < 2; ntp++)
            LDSM4(rg[ntp * 2][0], rg[ntp * 2][1], rg[ntp * 2 + 1][0], rg[ntp * 2 + 1][1],
                  b0 + ntp * 16 * RS);
    };
    auto mma8 = [&](uint32_t (&A)[2][4], uint32_t (&B)[4][2]) {
#pragma unroll
        for (int mt = 0; mt < 2; mt++)
#pragma unroll
            for (int nt = 0; nt < 4; nt++)
                mma16816h(acc[mt][nt], A[mt][0], A[mt][1], A[mt][2], A[mt][3],
                          B[nt][0], B[nt][1]);
    };

    const int NCH = GC / KC;    // 4
    load_chunk(0, 0);
    load_chunk(1, 1);
    CP_WAIT(1);
    __syncthreads();

    for (int c = 0; c < NCH; c++) {
        uint32_t stb = sb + (c & 1) * STAGE_B;
        ldA(aF[0], stb, 0);
        ldB(bF[0], stb, 0);
#pragma unroll
        for (int ks = 0; ks < 4; ks++) {
            int cur = ks & 1, nxt = cur ^ 1;
            if (ks < 3) { ldA(aF[nxt], stb, ks + 1); ldB(bF[nxt], stb, ks + 1); }
            mma8(aF[cur], bF[cur]);
        }
        if (c + 1 < NCH) {
            __syncthreads();
            if (c + 2 < NCH) { load_chunk(c + 2, c & 1); CP_WAIT(1); }
            else CP_WAIT(0);
            __syncthreads();
        }
    }

    // epilogue: bias + store
#pragma unroll
    for (int mt = 0; mt < 2; mt++) {
        int gm = mtile * 64 + warpM * 32 + mt * 16 + lr;
#pragma unroll
        for (int nt = 0; nt < 4; nt++) {
            int gn = ntile * 128 + warpN * 32 + nt * 8 + lc * 2;
            float2 bb = *(const float2*)&bias[gn];
            float2 o0, o1;
            o0.x = acc[mt][nt][0] + bb.x;
            o0.y = acc[mt][nt][1] + bb.y;
            o1.x = acc[mt][nt][2] + bb.x;
            o1.y = acc[mt][nt][3] + bb.y;
            *(float2*)&out[(size_t)gm * GHD + gn]       = o0;
            *(float2*)&out[(size_t)(gm + 8) * GHD + gn] = o1;
        }
    }
}

// ---------------- reduce stage 1: partial kv / ksum / vsum -----------------
#define RROWS 16

__global__ __launch_bounds__(256) void reduce_stage1(void)
{
    int chunk = blockIdx.x;
    int bh    = blockIdx.y;
    int b = bh >> 3, h = bh & 7;

    __shared__ float sk[RROWS][64];
    __shared__ float sv[RROWS][64];

    int tid  = threadIdx.x;
    int m    = tid & 63;
    int dg   = tid >> 6;
    int lane = tid & 31, warp = tid >> 5;
    int ldr = tid >> 4, ldc = (tid & 15) * 4;

    const float* kbase = g_k + (size_t)b * GN * GHD + h * GD;
    const float* vbase = g_v + (size_t)b * GN * GHD + h * GD;

    float acc[16];
#pragma unroll
    for (int j = 0; j < 16; j++) acc[j] = 0.f;
    float sacc = 0.f;

    int lend = (chunk + 1) * LCHUNK;
    for (int l0 = chunk * LCHUNK; l0 < lend; l0 += RROWS) {
        *(float4*)&sk[ldr][ldc] = *(const float4*)&kbase[(size_t)(l0 + ldr) * GHD + ldc];
        *(float4*)&sv[ldr][ldc] = *(const float4*)&vbase[(size_t)(l0 + ldr) * GHD + ldc];
        __syncthreads();
#pragma unroll
        for (int rr = 0; rr < 2; rr++) {
            int r = warp * 2 + rr;
            float x0 = sk[r][lane], x1 = sk[r][lane + 32];
            float ss = x0 * x0 + x1 * x1;
#pragma unroll
            for (int o = 16; o > 0; o >>= 1)
                ss += __shfl_xor_sync(0xffffffffu, ss, o);
            float inv = rsqrtf(ss);
            sk[r][lane]      = x0 * inv;
            sk[r][lane + 32] = x1 * inv;
        }
        __syncthreads();
#pragma unroll
        for (int r = 0; r < RROWS; r++) {
            float kval = sk[r][m];
            float4 v0 = *(const float4*)&sv[r][dg * 16 + 0];
            float4 v1 = *(const float4*)&sv[r][dg * 16 + 4];
            float4 v2 = *(const float4*)&sv[r][dg * 16 + 8];
            float4 v3 = *(const float4*)&sv[r][dg * 16 + 12];
            acc[0]  += kval * v0.x; acc[1]  += kval * v0.y;
            acc[2]  += kval * v0.z; acc[3]  += kval * v0.w;
            acc[4]  += kval * v1.x; acc[5]  += kval * v1.y;
            acc[6]  += kval * v1.z; acc[7]  += kval * v1.w;
            acc[8]  += kval * v2.x; acc[9]  += kval * v2.y;
            acc[10] += kval * v2.z; acc[11] += kval * v2.w;
            acc[12] += kval * v3.x; acc[13] += kval * v3.y;
            acc[14] += kval * v3.z; acc[15] += kval * v3.w;
            if (dg == 0)      sacc += kval;
            else if (dg == 1) sacc += sv[r][m];
        }
        __syncthreads();
    }

    float* dst = g_kvpart + ((size_t)chunk * 64 + bh) * 4224;
#pragma unroll
    for (int j = 0; j < 16; j++) dst[m * 64 + dg * 16 + j] = acc[j];
    if (dg == 0)      dst[4096 + m] = sacc;
    else if (dg == 1) dst[4160 + m] = sacc;
}

// ---------------- reduce stage 2 -------------------------------------------
__global__ void reduce_stage2(void)
{
    int i = blockIdx.x * blockDim.x + threadIdx.x;
    if (i >= 64 * 4224) return;
    float s = 0.f;
#pragma unroll 8
    for (int c = 0; c < CHUNKS; c++)
        s += g_kvpart[(size_t)c * 64 * 4224 + i];
    g_kvred[i] = s;
}

// ---------------- final ----------------------------------------------------
#define FROWS 64

__global__ __launch_bounds__(256) void final_kernel(float* __restrict__ out)
{
    __shared__ float sq[FROWS][GD];
    __shared__ float skv[GD][GD];
    __shared__ float sksum[GD];
    __shared__ float svsum[GD];
    __shared__ float sden[FROWS];

    int tid  = threadIdx.x;
    int dq   = tid & 15;
    int rg   = tid >> 4;
    int lane = tid & 31, warp = tid >> 5;

    size_t row0 = (size_t)blockIdx.x * FROWS;
    int b = (int)(row0 / GN);
    const float* qbase = g_q + row0 * GHD;
    const float Nf = (float)GN;

    float outacc[4][4];
#pragma unroll
    for (int i = 0; i < 4; i++)
#pragma unroll
        for (int j = 0; j < 4; j++) outacc[i][j] = 0.f;

    for (int h = 0; h < GH; h++) {
        const float* kvb = g_kvred + (size_t)(b * GH + h) * 4224;
#pragma unroll
        for (int t = 0; t < 4; t++)
            ((float4*)skv)[tid + t * 256] = ((const float4*)kvb)[tid + t * 256];
        if (tid < 64)        sksum[tid]      = kvb[4096 + tid];
        else if (tid < 128)  svsum[tid - 64] = kvb[4096 + tid];
#pragma unroll
        for (int t = 0; t < 16; t++) {
            int idx = tid + t * 256;
            int r = idx >> 6, c = idx & 63;
            sq[r][c] = qbase[(size_t)r * GHD + h * GD + c];
        }
        __syncthreads();

#pragma unroll
        for (int rr = 0; rr < 8; rr++) {
            int r = warp * 8 + rr;
            float x0 = sq[r][lane], x1 = sq[r][lane + 32];
            float ss = x0 * x0 + x1 * x1;
#pragma unroll
            for (int o = 16; o > 0; o >>= 1)
                ss += __shfl_xor_sync(0xffffffffu, ss, o);
            float inv = rsqrtf(ss);
            sq[r][lane]      = x0 * inv;
            sq[r][lane + 32] = x1 * inv;
        }
        __syncthreads();

#pragma unroll
        for (int rr = 0; rr < 8; rr++) {
            int r = warp * 8 + rr;
            float p = sq[r][lane] * sksum[lane] + sq[r][lane + 32] * sksum[lane + 32];
#pragma unroll
            for (int o = 16; o > 0; o >>= 1)
                p += __shfl_xor_sync(0xffffffffu, p, o);
            if (lane == 0) sden[r] = p + 2.f * Nf;
        }
        __syncthreads();

        // 4 rows x 4 d matvec, packed f32x2 math (2 FLOP / FFMA2)
        u64t a01[4], a23[4];
#pragma unroll
        for (int i = 0; i < 4; i++) { a01[i] = 0ull; a23[i] = 0ull; }

        for (int m = 0; m < GD; m++) {
            ulonglong2 kvp = *(const ulonglong2*)&skv[m][dq * 4];
#pragma unroll
            for (int i = 0; i < 4; i++) {
                float qv = sq[rg * 4 + i][m];
                u64t qq = pk2(qv, qv);
                FMA2(a01[i], qq, kvp.x, a01[i]);
                FMA2(a23[i], qq, kvp.y, a23[i]);
            }
        }
        float4 vsv = *(const float4*)&svsum[dq * 4];
#pragma unroll
        for (int i = 0; i < 4; i++) {
            float a0, a1, a2, a3;
            upk2(a0, a1, a01[i]);
            upk2(a2, a3, a23[i]);
            float rden = 1.f / sden[rg * 4 + i];
            outacc[i][0] += (a0 + Nf * vsv.x) * rden;
            outacc[i][1] += (a1 + Nf * vsv.y) * rden;
            outacc[i][2] += (a2 + Nf * vsv.z) * rden;
            outacc[i][3] += (a3 + Nf * vsv.w) * rden;
        }
        __syncthreads();
    }

#pragma unroll
    for (int i = 0; i < 4; i++) {
        float4 o;
        o.x = outacc[i][0] * (1.f / GH);
        o.y = outacc[i][1] * (1.f / GH);
        o.z = outacc[i][2] * (1.f / GH);
        o.w = outacc[i][3] * (1.f / GH);
        *(float4*)(out + (row0 + rg * 4 + i) * GD + dq * 4) = o;
    }
}

// ---------------- launch ---------------------------------------------------
extern "C" void kernel_launch(void* const* d_in, const int* in_sizes, int n_in,
                              void* d_out, int out_size)
{
    const float* q_in = (const float*)d_in[0];
    const float* s_in = (const float*)d_in[1];
    const float* Wq   = (const float*)d_in[2];
    const float* bq   = (const float*)d_in[3];
    const float* Wk   = (const float*)d_in[4];
    const float* bk   = (const float*)d_in[5];
    const float* Wv   = (const float*)d_in[6];
    const float* bv   = (const float*)d_in[7];
    float* out = (float*)d_out;

    float *gq, *gk, *gv;
    unsigned short *ah, *wh;
    cudaGetSymbolAddress((void**)&gq, g_q);
    cudaGetSymbolAddress((void**)&gk, g_k);
    cudaGetSymbolAddress((void**)&gv, g_v);
    cudaGetSymbolAddress((void**)&ah, g_Ah);
    cudaGetSymbolAddress((void**)&wh, g_WhT);

    static cudaStream_t s2 = nullptr;
    static cudaEvent_t evFork = nullptr, evJoin = nullptr;
    if (s2 == nullptr) {
        cudaFuncSetAttribute(gemm_mma, cudaFuncAttributeMaxDynamicSharedMemorySize, GEMM_SMEM);
        cudaStreamCreateWithFlags(&s2, cudaStreamNonBlocking);
        cudaEventCreateWithFlags(&evFork, cudaEventDisableTiming);
        cudaEventCreateWithFlags(&evJoin, cudaEventDisableTiming);
    }

    prep_weights<<<3 * GHD, 256>>>(Wq, Wk, Wv);
    prep_act<<<dim3(8192, 2), 256>>>(q_in, s_in);

    const size_t TA = (size_t)GM * GC;     // per-tensor activation plane size
    const size_t TW = (size_t)GHD * GC;    // per-matrix weight plane size
    dim3 ggrid(GHD / 128, GM / 64);        // (4, 2048)
    gemm_mma<<<ggrid, 256, GEMM_SMEM>>>(ah + TA, wh + TW,     bk, gk);
    gemm_mma<<<ggrid, 256, GEMM_SMEM>>>(ah + TA, wh + 2 * TW, bv, gv);

    // fork: q-projection (tensor-bound) overlaps the kv reduction (mem-bound)
    cudaEventRecord(evFork, 0);
    cudaStreamWaitEvent(s2, evFork, 0);
    gemm_mma<<<ggrid, 256, GEMM_SMEM, s2>>>(ah, wh, bq, gq);

    reduce_stage1<<<dim3(CHUNKS, 64), 256>>>();
    reduce_stage2<<<(64 * 4224 + 255) / 256, 256>>>();

    cudaEventRecord(evJoin, s2);
    cudaStreamWaitEvent(0, evJoin, 0);

    final_kernel<<<GM / FROWS, 256>>>(out);
}

// round 17
// speedup vs baseline: 2.5551x; 1.0132x over previous
#include <cuda_runtime.h>
#include <cuda_fp16.h>
#include <cstdint>

// Problem constants
#define GB 8
#define GN 16384
#define GC 256
#define GH 8
#define GD 64
#define GHD 512
#define GM (GB*GN)          // 131072 flattened rows

// ---------------- scratch (device globals; no allocation allowed) ----------
// projections stored fp16 (halves all downstream traffic)
__device__ __half g_qh[(size_t)GM * GHD];
__device__ __half g_kh[(size_t)GM * GHD];
__device__ __half g_vh[(size_t)GM * GHD];

// activation fp16 plane: [2 tensors][M][256]
__device__ unsigned short g_Ah[(size_t)2 * GM * GC];
// transposed fp16 weights: [3][N=512][K=256]
__device__ unsigned short g_WhT[3 * GHD * GC];

#define CHUNKS 64
#define LCHUNK (GN / CHUNKS)              // 256
// per (chunk, b*h): 4096 kv + 64 ksum + 64 vsum = 4224 floats
__device__ float g_kvpart[(size_t)CHUNKS * 64 * 4224];
__device__ float g_kvred[(size_t)64 * 4224];

// ======================= helpers ===========================================
__device__ __forceinline__ uint32_t smem_to_u32(const void* p) {
    uint32_t a;
    asm("{ .reg .u64 t; cvta.to.shared.u64 t, %1; cvt.u32.u64 %0, t; }" : "=r"(a) : "l"(p));
    return a;
}
#define CP_ASYNC16(dst, src) \
    asm volatile("cp.async.cg.shared.global [%0], [%1], 16;" :: "r"(dst), "l"(src))
#define CP_COMMIT() asm volatile("cp.async.commit_group;" ::: "memory")
#define CP_WAIT(n)  asm volatile("cp.async.wait_group %0;" :: "n"(n) : "memory")

#define LDSM4(r0, r1, r2, r3, addr) \
    asm volatile("ldmatrix.sync.aligned.m8n8.x4.shared.b16 {%0,%1,%2,%3}, [%4];" \
        : "=r"(r0), "=r"(r1), "=r"(r2), "=r"(r3) : "r"(addr))

__device__ __forceinline__ void mma16816h(float* c, uint32_t a0, uint32_t a1,
                                          uint32_t a2, uint32_t a3,
                                          uint32_t b0, uint32_t b1) {
    asm volatile(
        "mma.sync.aligned.m16n8k16.row.col.f32.f16.f16.f32 "
        "{%0,%1,%2,%3}, {%4,%5,%6,%7}, {%8,%9}, {%0,%1,%2,%3};"
        : "+f"(c[0]), "+f"(c[1]), "+f"(c[2]), "+f"(c[3])
        : "r"(a0), "r"(a1), "r"(a2), "r"(a3), "r"(b0), "r"(b1));
}

typedef unsigned long long u64t;
__device__ __forceinline__ u64t pk2(float lo, float hi) {
    u64t r;
    asm("mov.b64 %0, {%1, %2};" : "=l"(r) : "f"(lo), "f"(hi));
    return r;
}
__device__ __forceinline__ void upk2(float& lo, float& hi, u64t v) {
    asm("mov.b64 {%0, %1}, %2;" : "=f"(lo), "=f"(hi) : "l"(v));
}
#define FMA2(d, a, b, c) \
    asm("fma.rn.f32x2 %0, %1, %2, %3;" : "=l"(d) : "l"(a), "l"(b), "l"(c))

// ================= weight prep: transpose + fp16 ===========================
__global__ void prep_weights(const float* __restrict__ w0, const float* __restrict__ w1,
                             const float* __restrict__ w2)
{
    int m = blockIdx.x >> 9;          // 0..2
    int n = blockIdx.x & 511;         // 0..511
    int k = threadIdx.x;              // 0..255
    const float* W = (m == 0) ? w0 : (m == 1) ? w1 : w2;
    float x = W[(size_t)k * GHD + n];
    g_WhT[(size_t)m * GHD * GC + (size_t)n * GC + k] =
        __half_as_ushort(__float2half_rn(x));
}

// ================= activation prep: fp16 ===================================
__global__ void prep_act(const float* __restrict__ qin, const float* __restrict__ sin)
{
    const float* src = blockIdx.y ? sin : qin;
    unsigned short* dst = g_Ah + (size_t)blockIdx.y * GM * GC;
    const size_t NF4 = (size_t)GM * GC / 4;   // 8388608
#pragma unroll
    for (int j = 0; j < 4; j++) {
        size_t i = (size_t)j * 2097152 + (size_t)blockIdx.x * 256 + threadIdx.x;
        if (i >= NF4) break;
        float4 x = ((const float4*)src)[i];
        unsigned short hs[4];
        hs[0] = __half_as_ushort(__float2half_rn(x.x));
        hs[1] = __half_as_ushort(__float2half_rn(x.y));
        hs[2] = __half_as_ushort(__float2half_rn(x.z));
        hs[3] = __half_as_ushort(__float2half_rn(x.w));
        uint2 hp = {(uint32_t)hs[0] | ((uint32_t)hs[1] << 16),
                    (uint32_t)hs[2] | ((uint32_t)hs[3] << 16)};
        *(uint2*)&dst[i * 4] = hp;
    }
}

// ============ fp16 single-pass mma GEMM: out[M,512]=A@W^T+bias =============
// block tile 64(M) x 128(N), K chunks of 64 (4 k-steps), 2-stage cp.async,
// ldmatrix.x4 frag loads, fragment double-buffering, fp16 output.
#define KC 64
#define RS 144
#define PLANE_A (64 * RS)           // 9216
#define PLANE_Bp (128 * RS)         // 18432
#define OFF_B PLANE_A
#define STAGE_B (PLANE_A + PLANE_Bp)    // 27648
#define GEMM_SMEM (2 * STAGE_B)         // 55296

__global__ __launch_bounds__(256, 2)
void gemm_mma(const unsigned short* __restrict__ Ah,
              const unsigned short* __restrict__ Bh,
              const float* __restrict__ bias, __half* __restrict__ out)
{
    extern __shared__ char smem[];
    const uint32_t sb = smem_to_u32(smem);
    const int tid = threadIdx.x;
    const int lane = tid & 31, wid = tid >> 5;
    const int warpM = wid & 1;        // 2 warps in M (32 rows each)
    const int warpN = wid >> 1;       // 4 warps in N (32 cols each)
    const int lr = lane >> 2, lc = lane & 3;
    const int ntile = blockIdx.x;     // 0..3
    const int mtile = blockIdx.y;     // 0..2047

    const char* pA = (const char*)Ah + (size_t)mtile * 64 * 512;
    const char* pB = (const char*)Bh + (size_t)ntile * 128 * 512;

    float acc[2][4][4];
#pragma unroll
    for (int i = 0; i < 2; i++)
#pragma unroll
        for (int j = 0; j < 4; j++)
#pragma unroll
            for (int e = 0; e < 4; e++) acc[i][j][e] = 0.f;

    const uint32_t aRowBase =
        (uint32_t)(warpM * 32 + (lane & 7) + ((lane & 8) ? 8 : 0)) * RS
        + ((lane & 16) ? 16 : 0);
    const uint32_t bRowBase =
        (uint32_t)(warpN * 32 + (lane & 7) + ((lane & 16) ? 8 : 0)) * RS
        + ((lane & 8) ? 16 : 0);

    auto load_chunk = [&](int c, int s) {
        uint32_t sbase = sb + s * STAGE_B;
#pragma unroll
        for (int t = 0; t < 2; t++) {
            int w = tid + t * 256;
            int row = w >> 3, s4 = w & 7;
            CP_ASYNC16(sbase + row * RS + s4 * 16,
                       pA + (size_t)row * 512 + c * 128 + s4 * 16);
        }
#pragma unroll
        for (int t = 0; t < 4; t++) {
            int w = tid + t * 256;
            int row = w >> 3, s4 = w & 7;
            CP_ASYNC16(sbase + OFF_B + row * RS + s4 * 16,
                       pB + (size_t)row * 512 + c * 128 + s4 * 16);
        }
        CP_COMMIT();
    };

    uint32_t aF[2][2][4], bF[2][4][2];   // [parity][...]
    auto ldA = [&](uint32_t (&rg)[2][4], uint32_t stb, int ks) {
        uint32_t a0 = stb + aRowBase + ks * 32;
#pragma unroll
        for (int mt = 0; mt < 2; mt++)
            LDSM4(rg[mt][0], rg[mt][1], rg[mt][2], rg[mt][3], a0 + mt * 16 * RS);
    };
    auto ldB = [&](uint32_t (&rg)[4][2], uint32_t stb, int ks) {
        uint32_t b0 = stb + OFF_B + bRowBase + ks * 32;
#pragma unroll
        for (int ntp = 0; ntp < 2; ntp++)
            LDSM4(rg[ntp * 2][0], rg[ntp * 2][1], rg[ntp * 2 + 1][0], rg[ntp * 2 + 1][1],
                  b0 + ntp * 16 * RS);
    };
    auto mma8 = [&](uint32_t (&A)[2][4], uint32_t (&B)[4][2]) {
#pragma unroll
        for (int mt = 0; mt < 2; mt++)
#pragma unroll
            for (int nt = 0; nt < 4; nt++)
                mma16816h(acc[mt][nt], A[mt][0], A[mt][1], A[mt][2], A[mt][3],
                          B[nt][0], B[nt][1]);
    };

    const int NCH = GC / KC;    // 4
    load_chunk(0, 0);
    load_chunk(1, 1);
    CP_WAIT(1);
    __syncthreads();

    for (int c = 0; c < NCH; c++) {
        uint32_t stb = sb + (c & 1) * STAGE_B;
        ldA(aF[0], stb, 0);
        ldB(bF[0], stb, 0);
#pragma unroll
        for (int ks = 0; ks < 4; ks++) {
            int cur = ks & 1, nxt = cur ^ 1;
            if (ks < 3) { ldA(aF[nxt], stb, ks + 1); ldB(bF[nxt], stb, ks + 1); }
            mma8(aF[cur], bF[cur]);
        }
        if (c + 1 < NCH) {
            __syncthreads();
            if (c + 2 < NCH) { load_chunk(c + 2, c & 1); CP_WAIT(1); }
            else CP_WAIT(0);
            __syncthreads();
        }
    }

    // epilogue: bias + fp16 store
#pragma unroll
    for (int mt = 0; mt < 2; mt++) {
        int gm = mtile * 64 + warpM * 32 + mt * 16 + lr;
#pragma unroll
        for (int nt = 0; nt < 4; nt++) {
            int gn = ntile * 128 + warpN * 32 + nt * 8 + lc * 2;
            float2 bb = *(const float2*)&bias[gn];
            *(__half2*)&out[(size_t)gm * GHD + gn] =
                __floats2half2_rn(acc[mt][nt][0] + bb.x, acc[mt][nt][1] + bb.y);
            *(__half2*)&out[(size_t)(gm + 8) * GHD + gn] =
                __floats2half2_rn(acc[mt][nt][2] + bb.x, acc[mt][nt][3] + bb.y);
        }
    }
}

// ---------------- reduce stage 1: partial kv / ksum / vsum -----------------
#define RROWS 16

__global__ __launch_bounds__(256) void reduce_stage1(void)
{
    int chunk = blockIdx.x;
    int bh    = blockIdx.y;
    int b = bh >> 3, h = bh & 7;

    __shared__ float sk[RROWS][64];
    __shared__ float sv[RROWS][64];

    int tid  = threadIdx.x;
    int m    = tid & 63;
    int dg   = tid >> 6;
    int lane = tid & 31, warp = tid >> 5;
    int ldr = tid >> 4, ldc = (tid & 15) * 4;   // load row 0..15, 4 halves

    const __half* kbase = g_kh + (size_t)b * GN * GHD + h * GD;
    const __half* vbase = g_vh + (size_t)b * GN * GHD + h * GD;

    float acc[16];
#pragma unroll
    for (int j = 0; j < 16; j++) acc[j] = 0.f;
    float sacc = 0.f;

    int lend = (chunk + 1) * LCHUNK;
    for (int l0 = chunk * LCHUNK; l0 < lend; l0 += RROWS) {
        {
            uint2 kw = *(const uint2*)&kbase[(size_t)(l0 + ldr) * GHD + ldc];
            uint2 vw = *(const uint2*)&vbase[(size_t)(l0 + ldr) * GHD + ldc];
            float2 k0 = __half22float2(*reinterpret_cast<__half2*>(&kw.x));
            float2 k1 = __half22float2(*reinterpret_cast<__half2*>(&kw.y));
            float2 v0 = __half22float2(*reinterpret_cast<__half2*>(&vw.x));
            float2 v1 = __half22float2(*reinterpret_cast<__half2*>(&vw.y));
            sk[ldr][ldc + 0] = k0.x; sk[ldr][ldc + 1] = k0.y;
            sk[ldr][ldc + 2] = k1.x; sk[ldr][ldc + 3] = k1.y;
            sv[ldr][ldc + 0] = v0.x; sv[ldr][ldc + 1] = v0.y;
            sv[ldr][ldc + 2] = v1.x; sv[ldr][ldc + 3] = v1.y;
        }
        __syncthreads();
#pragma unroll
        for (int rr = 0; rr < 2; rr++) {
            int r = warp * 2 + rr;
            float x0 = sk[r][lane], x1 = sk[r][lane + 32];
            float ss = x0 * x0 + x1 * x1;
#pragma unroll
            for (int o = 16; o > 0; o >>= 1)
                ss += __shfl_xor_sync(0xffffffffu, ss, o);
            float inv = rsqrtf(ss);
            sk[r][lane]      = x0 * inv;
            sk[r][lane + 32] = x1 * inv;
        }
        __syncthreads();
#pragma unroll
        for (int r = 0; r < RROWS; r++) {
            float kval = sk[r][m];
            float4 v0 = *(const float4*)&sv[r][dg * 16 + 0];
            float4 v1 = *(const float4*)&sv[r][dg * 16 + 4];
            float4 v2 = *(const float4*)&sv[r][dg * 16 + 8];
            float4 v3 = *(const float4*)&sv[r][dg * 16 + 12];
            acc[0]  += kval * v0.x; acc[1]  += kval * v0.y;
            acc[2]  += kval * v0.z; acc[3]  += kval * v0.w;
            acc[4]  += kval * v1.x; acc[5]  += kval * v1.y;
            acc[6]  += kval * v1.z; acc[7]  += kval * v1.w;
            acc[8]  += kval * v2.x; acc[9]  += kval * v2.y;
            acc[10] += kval * v2.z; acc[11] += kval * v2.w;
            acc[12] += kval * v3.x; acc[13] += kval * v3.y;
            acc[14] += kval * v3.z; acc[15] += kval * v3.w;
            if (dg == 0)      sacc += kval;
            else if (dg == 1) sacc += sv[r][m];
        }
        __syncthreads();
    }

    float* dst = g_kvpart + ((size_t)chunk * 64 + bh) * 4224;
#pragma unroll
    for (int j = 0; j < 16; j++) dst[m * 64 + dg * 16 + j] = acc[j];
    if (dg == 0)      dst[4096 + m] = sacc;
    else if (dg == 1) dst[4160 + m] = sacc;
}

// ---------------- reduce stage 2 -------------------------------------------
__global__ void reduce_stage2(void)
{
    int i = blockIdx.x * blockDim.x + threadIdx.x;
    if (i >= 64 * 4224) return;
    float s = 0.f;
#pragma unroll 8
    for (int c = 0; c < CHUNKS; c++)
        s += g_kvpart[(size_t)c * 64 * 4224 + i];
    g_kvred[i] = s;
}

// ---------------- final ----------------------------------------------------
#define FROWS 64

__global__ __launch_bounds__(256) void final_kernel(float* __restrict__ out)
{
    __shared__ float sq[FROWS][GD];
    __shared__ float skv[GD][GD];
    __shared__ float sksum[GD];
    __shared__ float svsum[GD];
    __shared__ float sden[FROWS];

    int tid  = threadIdx.x;
    int dq   = tid & 15;
    int rg   = tid >> 4;
    int lane = tid & 31, warp = tid >> 5;

    size_t row0 = (size_t)blockIdx.x * FROWS;
    int b = (int)(row0 / GN);
    const __half* qbase = g_qh + row0 * GHD;
    const float Nf = (float)GN;

    float outacc[4][4];
#pragma unroll
    for (int i = 0; i < 4; i++)
#pragma unroll
        for (int j = 0; j < 4; j++) outacc[i][j] = 0.f;

    for (int h = 0; h < GH; h++) {
        const float* kvb = g_kvred + (size_t)(b * GH + h) * 4224;
#pragma unroll
        for (int t = 0; t < 4; t++)
            ((float4*)skv)[tid + t * 256] = ((const float4*)kvb)[tid + t * 256];
        if (tid < 64)        sksum[tid]      = kvb[4096 + tid];
        else if (tid < 128)  svsum[tid - 64] = kvb[4096 + tid];
        // q slice: 64 rows x 64 cols fp16 -> fp32 smem (2048 half2)
#pragma unroll
        for (int t = 0; t < 8; t++) {
            int idx = tid + t * 256;
            int r = idx >> 5, c2 = idx & 31;
            __half2 hv = *(const __half2*)&qbase[(size_t)r * GHD + h * GD + c2 * 2];
            float2 f = __half22float2(hv);
            sq[r][c2 * 2]     = f.x;
            sq[r][c2 * 2 + 1] = f.y;
        }
        __syncthreads();

#pragma unroll
        for (int rr = 0; rr < 8; rr++) {
            int r = warp * 8 + rr;
            float x0 = sq[r][lane], x1 = sq[r][lane + 32];
            float ss = x0 * x0 + x1 * x1;
#pragma unroll
            for (int o = 16; o > 0; o >>= 1)
                ss += __shfl_xor_sync(0xffffffffu, ss, o);
            float inv = rsqrtf(ss);
            sq[r][lane]      = x0 * inv;
            sq[r][lane + 32] = x1 * inv;
        }
        __syncthreads();

#pragma unroll
        for (int rr = 0; rr < 8; rr++) {
            int r = warp * 8 + rr;
            float p = sq[r][lane] * sksum[lane] + sq[r][lane + 32] * sksum[lane + 32];
#pragma unroll
            for (int o = 16; o > 0; o >>= 1)
                p += __shfl_xor_sync(0xffffffffu, p, o);
            if (lane == 0) sden[r] = p + 2.f * Nf;
        }
        __syncthreads();

        // 4 rows x 4 d matvec, packed f32x2 math (2 FLOP / FFMA2)
        u64t a01[4], a23[4];
#pragma unroll
        for (int i = 0; i < 4; i++) { a01[i] = 0ull; a23[i] = 0ull; }

        for (int m = 0; m < GD; m++) {
            ulonglong2 kvp = *(const ulonglong2*)&skv[m][dq * 4];
#pragma unroll
            for (int i = 0; i < 4; i++) {
                float qv = sq[rg * 4 + i][m];
                u64t qq = pk2(qv, qv);
                FMA2(a01[i], qq, kvp.x, a01[i]);
                FMA2(a23[i], qq, kvp.y, a23[i]);
            }
        }
        float4 vsv = *(const float4*)&svsum[dq * 4];
#pragma unroll
        for (int i = 0; i < 4; i++) {
            float a0, a1, a2, a3;
            upk2(a0, a1, a01[i]);
            upk2(a2, a3, a23[i]);
            float rden = 1.f / sden[rg * 4 + i];
            outacc[i][0] += (a0 + Nf * vsv.x) * rden;
            outacc[i][1] += (a1 + Nf * vsv.y) * rden;
            outacc[i][2] += (a2 + Nf * vsv.z) * rden;
            outacc[i][3] += (a3 + Nf * vsv.w) * rden;
        }
        __syncthreads();
    }

#pragma unroll
    for (int i = 0; i < 4; i++) {
        float4 o;
        o.x = outacc[i][0] * (1.f / GH);
        o.y = outacc[i][1] * (1.f / GH);
        o.z = outacc[i][2] * (1.f / GH);
        o.w = outacc[i][3] * (1.f / GH);
        *(float4*)(out + (row0 + rg * 4 + i) * GD + dq * 4) = o;
    }
}

// ---------------- launch ---------------------------------------------------
extern "C" void kernel_launch(void* const* d_in, const int* in_sizes, int n_in,
                              void* d_out, int out_size)
{
    const float* q_in = (const float*)d_in[0];
    const float* s_in = (const float*)d_in[1];
    const float* Wq   = (const float*)d_in[2];
    const float* bq   = (const float*)d_in[3];
    const float* Wk   = (const float*)d_in[4];
    const float* bk   = (const float*)d_in[5];
    const float* Wv   = (const float*)d_in[6];
    const float* bv   = (const float*)d_in[7];
    float* out = (float*)d_out;

    __half *gq, *gk, *gv;
    unsigned short *ah, *wh;
    cudaGetSymbolAddress((void**)&gq, g_qh);
    cudaGetSymbolAddress((void**)&gk, g_kh);
    cudaGetSymbolAddress((void**)&gv, g_vh);
    cudaGetSymbolAddress((void**)&ah, g_Ah);
    cudaGetSymbolAddress((void**)&wh, g_WhT);

    static cudaStream_t s2 = nullptr;
    static cudaEvent_t evFork = nullptr, evJoin = nullptr;
    if (s2 == nullptr) {
        cudaFuncSetAttribute(gemm_mma, cudaFuncAttributeMaxDynamicSharedMemorySize, GEMM_SMEM);
        cudaStreamCreateWithFlags(&s2, cudaStreamNonBlocking);
        cudaEventCreateWithFlags(&evFork, cudaEventDisableTiming);
        cudaEventCreateWithFlags(&evJoin, cudaEventDisableTiming);
    }

    prep_weights<<<3 * GHD, 256>>>(Wq, Wk, Wv);
    prep_act<<<dim3(8192, 2), 256>>>(q_in, s_in);

    const size_t TA = (size_t)GM * GC;     // per-tensor activation plane size
    const size_t TW = (size_t)GHD * GC;    // per-matrix weight plane size
    dim3 ggrid(GHD / 128, GM / 64);        // (4, 2048)
    gemm_mma<<<ggrid, 256, GEMM_SMEM>>>(ah + TA, wh + TW,     bk, gk);
    gemm_mma<<<ggrid, 256, GEMM_SMEM>>>(ah + TA, wh + 2 * TW, bv, gv);

    // fork: q-projection overlaps the kv reduction
    cudaEventRecord(evFork, 0);
    cudaStreamWaitEvent(s2, evFork, 0);
    gemm_mma<<<ggrid, 256, GEMM_SMEM, s2>>>(ah, wh, bq, gq);

    reduce_stage1<<<dim3(CHUNKS, 64), 256>>>();
    reduce_stage2<<<(64 * 4224 + 255) / 256, 256>>>();

    cudaEventRecord(evJoin, s2);
    cudaStreamWaitEvent(0, evJoin, 0);

    final_kernel<<<GM / FROWS, 256>>>(out);
}